// round 9
// baseline (speedup 1.0000x reference)
#include <cuda_runtime.h>
#include <cuda_fp16.h>
#include <math.h>
#include <stdint.h>

#define D_MODEL 1024
#define D_STATE 128
#define SEQ_LEN 4096
#define BATCH   4
#define ROWS    (BATCH * SEQ_LEN)        // 16384
#define LN_EPS  1e-3f
#define NPROJ   384
#define KCAT    1152                     // [W_in·D ; W_so] rows

// ---------------- scratch (allocation-free: __device__ globals) ----------------
// int8 activation limb planes + row scales
__device__ uint32_t g_a1[(size_t)ROWS * 256];          // xn limb1, 4 bytes/thread-col
__device__ uint32_t g_a2[(size_t)ROWS * 256];          // xn limb2
__device__ float    g_sa[ROWS];
__device__ int8_t   g_y1[(size_t)ROWS * D_STATE];      // ysc limb1
__device__ int8_t   g_y2[(size_t)ROWS * D_STATE];
__device__ float    g_sy[ROWS];
__device__ float    g_proj[(size_t)ROWS * NPROJ];
// fp16 splits for precompute GEMMs
__device__ __half g_WinA [(size_t)D_MODEL * 2 * D_MODEL];
__device__ __half g_WcatA[(size_t)KCAT    * 2 * D_MODEL];
__device__ __half g_WpkB [(size_t)NPROJ   * 2 * D_MODEL];
__device__ __half g_WoutB[(size_t)D_MODEL * 2 * D_MODEL];
// combined weights fp32 ([n][k]) then quantized limbs
__device__ float  g_W4f [(size_t)NPROJ   * D_MODEL];
__device__ float  g_Wcatf[(size_t)D_MODEL * KCAT];
__device__ int8_t g_W4q1[(size_t)NPROJ * D_MODEL],  g_W4q2[(size_t)NPROJ * D_MODEL];
__device__ int8_t g_W3q1[(size_t)D_MODEL * D_MODEL], g_W3q2[(size_t)D_MODEL * D_MODEL];
__device__ int8_t g_W1q1[(size_t)D_MODEL * D_STATE], g_W1q2[(size_t)D_MODEL * D_STATE];
__device__ float g_swc4[NPROJ], g_swc3[D_MODEL], g_swc1[D_MODEL];
__device__ float g_b4[NPROJ], g_b5[D_MODEL];
__device__ float g_carry[BATCH * 64 * D_STATE];

// ---------------- helpers ----------------
__device__ __forceinline__ uint32_t cvta_smem(const void* p) {
    uint32_t a;
    asm("{ .reg .u64 t; cvta.to.shared.u64 t, %1; cvt.u32.u64 %0, t; }" : "=r"(a) : "l"(p));
    return a;
}
__device__ __forceinline__ uint32_t pack4b(int a, int b, int c, int d) {
    return (uint32_t)(a & 0xff) | ((uint32_t)(b & 0xff) << 8) |
           ((uint32_t)(c & 0xff) << 16) | ((uint32_t)(d & 0xff) << 24);
}
__device__ __forceinline__ void quant2(float v, float qs, int& i1, int& i2) {
    float q  = v * qs;
    float f1 = rintf(q);
    float f2 = rintf((q - f1) * 256.f);
    f2 = fminf(fmaxf(f2, -128.f), 127.f);
    i1 = (int)f1; i2 = (int)f2;
}

#define MMA_F16(d, a, b) \
    asm volatile( \
        "mma.sync.aligned.m16n8k16.row.col.f32.f16.f16.f32 " \
        "{%0,%1,%2,%3}, {%4,%5,%6,%7}, {%8,%9}, {%0,%1,%2,%3};" \
        : "+f"((d)[0]), "+f"((d)[1]), "+f"((d)[2]), "+f"((d)[3]) \
        : "r"((a)[0]), "r"((a)[1]), "r"((a)[2]), "r"((a)[3]), \
          "r"((b)[0]), "r"((b)[1]))

#define MMA_S8(d, a, b0, b1) \
    asm volatile( \
        "mma.sync.aligned.m16n8k32.row.col.s32.s8.s8.s32 " \
        "{%0,%1,%2,%3}, {%4,%5,%6,%7}, {%8,%9}, {%0,%1,%2,%3};" \
        : "+r"((d)[0]), "+r"((d)[1]), "+r"((d)[2]), "+r"((d)[3]) \
        : "r"((a)[0]), "r"((a)[1]), "r"((a)[2]), "r"((a)[3]), \
          "r"(b0), "r"(b1))

#define LDSM_X4(r, addr) \
    asm volatile("ldmatrix.sync.aligned.m8n8.x4.shared.b16 {%0,%1,%2,%3}, [%4];" \
        : "=r"((r)[0]), "=r"((r)[1]), "=r"((r)[2]), "=r"((r)[3]) : "r"(addr))

// ---------------- LayerNorm -> int8 limbs + row scale ----------------
__global__ __launch_bounds__(256) void ln_q_kernel(
    const float* __restrict__ x, const float* __restrict__ gamma,
    const float* __restrict__ beta, uint32_t* __restrict__ a1p,
    uint32_t* __restrict__ a2p, float* __restrict__ sa)
{
    int row = blockIdx.x;
    int tid = threadIdx.x;
    const float4* xr = (const float4*)(x + (size_t)row * D_MODEL);
    float4 v = xr[tid];

    float s  = v.x + v.y + v.z + v.w;
    float sq = v.x*v.x + v.y*v.y + v.z*v.z + v.w*v.w;
    #pragma unroll
    for (int o = 16; o > 0; o >>= 1) {
        s  += __shfl_xor_sync(0xffffffffu, s,  o);
        sq += __shfl_xor_sync(0xffffffffu, sq, o);
    }
    __shared__ float sh_s[8], sh_q[8], sh_m[8];
    int wid = tid >> 5, lid = tid & 31;
    if (lid == 0) { sh_s[wid] = s; sh_q[wid] = sq; }
    __syncthreads();
    if (wid == 0) {
        float a = (lid < 8) ? sh_s[lid] : 0.f;
        float b = (lid < 8) ? sh_q[lid] : 0.f;
        #pragma unroll
        for (int o = 4; o > 0; o >>= 1) {
            a += __shfl_xor_sync(0xffffffffu, a, o);
            b += __shfl_xor_sync(0xffffffffu, b, o);
        }
        if (lid == 0) { sh_s[0] = a; sh_q[0] = b; }
    }
    __syncthreads();
    float mu   = sh_s[0] * (1.0f / D_MODEL);
    float var  = sh_q[0] * (1.0f / D_MODEL) - mu * mu;
    float rstd = rsqrtf(var + LN_EPS);

    float4 gv = ((const float4*)gamma)[tid];
    float4 bv = ((const float4*)beta)[tid];
    float o0 = (v.x - mu) * rstd * gv.x + bv.x;
    float o1 = (v.y - mu) * rstd * gv.y + bv.y;
    float o2 = (v.z - mu) * rstd * gv.z + bv.z;
    float o3 = (v.w - mu) * rstd * gv.w + bv.w;

    // row max of |o|
    float m = fmaxf(fmaxf(fabsf(o0), fabsf(o1)), fmaxf(fabsf(o2), fabsf(o3)));
    #pragma unroll
    for (int o = 16; o > 0; o >>= 1) m = fmaxf(m, __shfl_xor_sync(0xffffffffu, m, o));
    if (lid == 0) sh_m[wid] = m;
    __syncthreads();
    if (wid == 0) {
        float a = (lid < 8) ? sh_m[lid] : 0.f;
        #pragma unroll
        for (int o = 4; o > 0; o >>= 1) a = fmaxf(a, __shfl_xor_sync(0xffffffffu, a, o));
        if (lid == 0) sh_m[0] = a;
    }
    __syncthreads();
    float amax = fmaxf(sh_m[0], 1e-20f);
    float qs = 127.f / amax;

    int p10, p20, p11, p21, p12, p22, p13, p23;
    quant2(o0, qs, p10, p20);
    quant2(o1, qs, p11, p21);
    quant2(o2, qs, p12, p22);
    quant2(o3, qs, p13, p23);
    a1p[row * 256 + tid] = pack4b(p10, p11, p12, p13);
    a2p[row * 256 + tid] = pack4b(p20, p21, p22, p23);
    if (tid == 0) sa[row] = amax * (1.f / 127.f);
}

// ---------------- prep: fp16 splits for precompute GEMMs ----------------
__global__ void prep_split_A(const float* __restrict__ X, __half* __restrict__ XA,
                             int M, int K)
{
    int idx = blockIdx.x * blockDim.x + threadIdx.x;
    if (idx >= M * K) return;
    int m = idx / K, k = idx % K;
    float w = X[idx];
    __half hi = __float2half_rn(w);
    __half lo = __float2half_rn(w - __half2float(hi));
    size_t base = (size_t)m * 2 * K;
    XA[base + k]     = hi;
    XA[base + K + k] = lo;
}

// A = [W_in * diag(D) ; W_so]  (KCAT x 1024), split hi/lo
__global__ void prep_catA(const float* __restrict__ W_in, const float* __restrict__ D,
                          const float* __restrict__ W_so, __half* __restrict__ XA)
{
    int idx = blockIdx.x * blockDim.x + threadIdx.x;
    if (idx >= KCAT * D_MODEL) return;
    int m = idx / D_MODEL, j = idx % D_MODEL;
    float w = (m < D_MODEL) ? (W_in[(size_t)m * D_MODEL + j] * D[j])
                            : W_so[(size_t)(m - D_MODEL) * D_MODEL + j];
    __half hi = __float2half_rn(w);
    __half lo = __float2half_rn(w - __half2float(hi));
    size_t base = (size_t)m * 2 * D_MODEL;
    XA[base + j]           = hi;
    XA[base + D_MODEL + j] = lo;
}

// B = [W_xs | W_B | W_C]^T  (384 x 1024), split hi/lo
__global__ void prep_pkB(const float* __restrict__ Wxs, const float* __restrict__ WB,
                         const float* __restrict__ WC, __half* __restrict__ XB)
{
    int idx = blockIdx.x * blockDim.x + threadIdx.x;
    if (idx >= NPROJ * D_MODEL) return;
    int n = idx / D_MODEL, j = idx % D_MODEL;
    float w;
    if (n < 128)      w = Wxs[(size_t)j * 128 + n];
    else if (n < 256) w = WB [(size_t)j * 128 + (n - 128)];
    else              w = WC [(size_t)j * 128 + (n - 256)];
    __half hi = __float2half_rn(w);
    __half lo = __float2half_rn(w - __half2float(hi));
    size_t base = (size_t)n * 2 * D_MODEL;
    XB[base + j]           = hi;
    XB[base + D_MODEL + j] = lo;
}

// B = W_out^T (1024 x 1024), split hi/lo
__global__ void prep_outB(const float* __restrict__ W, __half* __restrict__ XB)
{
    int idx = blockIdx.x * blockDim.x + threadIdx.x;
    if (idx >= D_MODEL * D_MODEL) return;
    int j = idx / D_MODEL, n = idx % D_MODEL;
    float w = W[idx];
    __half hi = __float2half_rn(w);
    __half lo = __float2half_rn(w - __half2float(hi));
    size_t base = (size_t)n * 2 * D_MODEL;
    XB[base + j]           = hi;
    XB[base + D_MODEL + j] = lo;
}

// ---------------- bias precompute ----------------
__global__ void bias4_k(const float* __restrict__ b_in,
                        const float* __restrict__ W_xs, const float* __restrict__ W_B,
                        const float* __restrict__ bB,  const float* __restrict__ W_C,
                        const float* __restrict__ bC,  float* __restrict__ b4)
{
    int n = blockIdx.x * 128 + threadIdx.x;
    float acc = 0.f;
    if (n < 128) {
        for (int j = 0; j < D_MODEL; j++) acc += b_in[j] * W_xs[j * 128 + n];
        b4[n] = acc;
    } else if (n < 256) {
        int c = n - 128;
        for (int j = 0; j < D_MODEL; j++) acc += b_in[j] * W_B[j * 128 + c];
        b4[n] = acc + bB[c];
    } else {
        int c = n - 256;
        for (int j = 0; j < D_MODEL; j++) acc += b_in[j] * W_C[j * 128 + c];
        b4[n] = acc + bC[c];
    }
}

__global__ void bias5_k(const float* __restrict__ b_in, const float* __restrict__ D,
                        const float* __restrict__ W_out, const float* __restrict__ b_out,
                        float* __restrict__ b5)
{
    int n = blockIdx.x * 256 + threadIdx.x;
    float acc = 0.f;
    for (int j = 0; j < D_MODEL; j++) acc += b_in[j] * D[j] * W_out[j * D_MODEL + n];
    b5[n] = acc + b_out[n];
}

// ---------------- precompute GEMM (3-term fp16 dual split -> fp32 [n][k]) ----------------
#define PBM 128
#define PBN 64
#define PRSB 80
#define PTILEA (PBM * PRSB)
#define PSTAGE ((PBM + PBN) * PRSB)
#define PGSM (3 * PSTAGE)

__global__ __launch_bounds__(256, 2)
void pgemm(const __half* __restrict__ A, const __half* __restrict__ B, int K,
           float* __restrict__ Wf, int ldw)
{
    extern __shared__ __align__(128) char smem[];
    const int tid  = threadIdx.x;
    const int warp = tid >> 5, lane = tid & 31;
    const int wm = warp & 1, wn = warp >> 1;
    const int m0 = blockIdx.y * PBM, n0 = blockIdx.x * PBN;
    const uint32_t smem_base = cvta_smem(smem);

    const int KB = K / 32;
    const int NK = 3 * KB;
    const size_t row_bytes = (size_t)K * 4;
    const __half* Ab = A + (size_t)m0 * 2 * K;
    const __half* Bb = B + (size_t)n0 * 2 * K;

    float acc[4][2][4];
    #pragma unroll
    for (int i = 0; i < 4; i++)
        #pragma unroll
        for (int j = 0; j < 2; j++)
            #pragma unroll
            for (int e = 0; e < 4; e++) acc[i][j][e] = 0.f;

    auto load_stage = [&](int sk, int buf) {
        const uint32_t sb = smem_base + buf * PSTAGE;
        int lkA = (sk < 2 * KB) ? sk : sk - 2 * KB;   // A: [hi|lo|hi]
        int lkB = (sk < KB)     ? sk : sk - KB;       // B: [hi|hi|lo]
        const size_t kbA = (size_t)lkA * 64;
        const size_t kbB = (size_t)lkB * 64;
        #pragma unroll
        for (int j = 0; j < 2; j++) {
            int chunk = tid + j * 256;
            int row = chunk >> 2, cb = chunk & 3;
            const char* ga = (const char*)Ab + (size_t)row * row_bytes + kbA + cb * 16;
            asm volatile("cp.async.cg.shared.global [%0], [%1], 16;"
                         :: "r"(sb + row * PRSB + cb * 16), "l"(ga));
        }
        {
            int row = tid >> 2, cb = tid & 3;
            const char* gb = (const char*)Bb + (size_t)row * row_bytes + kbB + cb * 16;
            asm volatile("cp.async.cg.shared.global [%0], [%1], 16;"
                         :: "r"(sb + PTILEA + row * PRSB + cb * 16), "l"(gb));
        }
        asm volatile("cp.async.commit_group;");
    };

    #pragma unroll
    for (int s = 0; s < 2; s++) load_stage(s, s);

    const uint32_t lrow = (lane & 15);
    const uint32_t lkb  = (lane >> 4) * 16;

    for (int i = 0; i < NK; i++) {
        asm volatile("cp.async.wait_group 1;");
        __syncthreads();
        int nxt = i + 2;
        if (nxt < NK) load_stage(nxt, nxt % 3);
        else          asm volatile("cp.async.commit_group;");

        const uint32_t sb = smem_base + (i % 3) * PSTAGE;
        const uint32_t abase = sb + (wm * 64) * PRSB;
        const uint32_t bbase = sb + PTILEA + (wn * 16) * PRSB;

        #pragma unroll
        for (int ks = 0; ks < 2; ks++) {
            uint32_t Af[4][4], Bf[4];
            #pragma unroll
            for (int mt = 0; mt < 4; mt++)
                LDSM_X4(Af[mt], abase + (mt * 16 + lrow) * PRSB + ks * 32 + lkb);
            LDSM_X4(Bf, bbase + lrow * PRSB + ks * 32 + lkb);

            #pragma unroll
            for (int mt = 0; mt < 4; mt++) {
                #pragma unroll
                for (int nt = 0; nt < 2; nt++) {
                    uint32_t b2[2] = { Bf[nt], Bf[nt + 2] };
                    MMA_F16(acc[mt][nt], Af[mt], b2);
                }
            }
        }
    }

    // scatter fp32: Wf[n][k]  (n = col of C, k = row of C)
    const int groupID = lane >> 2, tig = lane & 3;
    #pragma unroll
    for (int mt = 0; mt < 4; mt++) {
        #pragma unroll
        for (int nt = 0; nt < 2; nt++) {
            int r0 = m0 + wm * 64 + mt * 16 + groupID;
            int c0 = n0 + wn * 16 + nt * 8 + tig * 2;
            Wf[(size_t)c0 * ldw + r0]           = acc[mt][nt][0];
            Wf[(size_t)(c0 + 1) * ldw + r0]     = acc[mt][nt][1];
            Wf[(size_t)c0 * ldw + r0 + 8]       = acc[mt][nt][2];
            Wf[(size_t)(c0 + 1) * ldw + r0 + 8] = acc[mt][nt][3];
        }
    }
}

// ---------------- weight quantizers ----------------
__device__ __forceinline__ float blockmax128(float m, float* sh) {
    #pragma unroll
    for (int o = 16; o > 0; o >>= 1) m = fmaxf(m, __shfl_xor_sync(0xffffffffu, m, o));
    int wid = threadIdx.x >> 5;
    if ((threadIdx.x & 31) == 0) sh[wid] = m;
    __syncthreads();
    float r = fmaxf(fmaxf(sh[0], sh[1]), fmaxf(sh[2], sh[3]));
    __syncthreads();
    return r;
}

__global__ __launch_bounds__(128) void quant_w4(const float* __restrict__ Wf,
                                                int8_t* __restrict__ q1, int8_t* __restrict__ q2,
                                                float* __restrict__ swc)
{
    __shared__ float sh[4];
    int n = blockIdx.x, tid = threadIdx.x;
    const float* row = Wf + (size_t)n * D_MODEL;
    float m = 0.f;
    for (int k = tid; k < D_MODEL; k += 128) m = fmaxf(m, fabsf(row[k]));
    m = blockmax128(m, sh);
    m = fmaxf(m, 1e-20f);
    float qs = 127.f / m;
    for (int k = tid; k < D_MODEL; k += 128) {
        int i1, i2; quant2(row[k], qs, i1, i2);
        q1[(size_t)n * D_MODEL + k] = (int8_t)i1;
        q2[(size_t)n * D_MODEL + k] = (int8_t)i2;
    }
    if (tid == 0) swc[n] = m * (1.f / 127.f);
}

__global__ __launch_bounds__(128) void quant_wcat(const float* __restrict__ Wf,
    int8_t* __restrict__ q31, int8_t* __restrict__ q32, float* __restrict__ swc3,
    int8_t* __restrict__ q11, int8_t* __restrict__ q12, float* __restrict__ swc1)
{
    __shared__ float sh[4];
    int n = blockIdx.x, tid = threadIdx.x;
    const float* row = Wf + (size_t)n * KCAT;
    float m1 = 0.f;
    for (int k = tid; k < D_MODEL; k += 128) m1 = fmaxf(m1, fabsf(row[k]));
    m1 = blockmax128(m1, sh);
    float m2 = fabsf(row[D_MODEL + tid]);
    m2 = blockmax128(m2, sh);
    m1 = fmaxf(m1, 1e-20f); m2 = fmaxf(m2, 1e-20f);
    float qs1 = 127.f / m1, qs2 = 127.f / m2;
    for (int k = tid; k < D_MODEL; k += 128) {
        int i1, i2; quant2(row[k], qs1, i1, i2);
        q31[(size_t)n * D_MODEL + k] = (int8_t)i1;
        q32[(size_t)n * D_MODEL + k] = (int8_t)i2;
    }
    {
        int i1, i2; quant2(row[D_MODEL + tid], qs2, i1, i2);
        q11[(size_t)n * D_STATE + tid] = (int8_t)i1;
        q12[(size_t)n * D_STATE + tid] = (int8_t)i2;
    }
    if (tid == 0) { swc3[n] = m1 * (1.f / 127.f); swc1[n] = m2 * (1.f / 127.f); }
}

// ---------------- int8 GEMM: C = dequant(A1W1 + (A1W2 + A2W1)/256) ----------------
// CTA 128x128, 16 warps (2M x 8N), warp tile 64x16, BK=64 (2 k32-iters/stage), 3 stages.
#define BM 128
#define BN 128
#define QRSB 80
#define QPL (BM * QRSB)                  // 10240 per plane
#define QSTAGE (4 * QPL)                 // 40960: A1|A2|B1|B2
#define QGSM (3 * QSTAGE)                // 122880

template<bool HAS_BIAS, bool HAS_RES>
__global__ __launch_bounds__(512, 1)
void qgemm(const int8_t* __restrict__ A1, const int8_t* __restrict__ A2, int lda,
           const int8_t* __restrict__ B1, const int8_t* __restrict__ B2, int K,
           int Nc, const float* __restrict__ sa, const float* __restrict__ swc,
           float* __restrict__ Cf, const float* __restrict__ bias,
           const float* __restrict__ res)
{
    extern __shared__ __align__(128) char smem[];
    const int tid  = threadIdx.x;
    const int warp = tid >> 5, lane = tid & 31;
    const int wm = warp & 1, wn = warp >> 1;           // 2 x 8
    const int m0 = blockIdx.y * BM, n0 = blockIdx.x * BN;
    const uint32_t smem_base = cvta_smem(smem);

    const int NKP = K / 64;                            // stages along K
    const char* Ab1 = (const char*)A1 + (size_t)m0 * lda;
    const char* Ab2 = (const char*)A2 + (size_t)m0 * lda;
    const char* Bb1 = (const char*)B1 + (size_t)n0 * K;
    const char* Bb2 = (const char*)B2 + (size_t)n0 * K;

    int acc1[4][2][4], accX[4][2][4];
    #pragma unroll
    for (int i = 0; i < 4; i++)
        #pragma unroll
        for (int j = 0; j < 2; j++)
            #pragma unroll
            for (int e = 0; e < 4; e++) { acc1[i][j][e] = 0; accX[i][j][e] = 0; }

    auto load_stage = [&](int sk, int buf) {
        const uint32_t sb = smem_base + buf * QSTAGE;
        const size_t kb = (size_t)sk * 64;
        int row = tid >> 2, cb = tid & 3;              // 512 = 128 rows x 4 chunks
        uint32_t doff = row * QRSB + cb * 16;
        size_t srcoff = kb + cb * 16;
        asm volatile("cp.async.cg.shared.global [%0], [%1], 16;"
                     :: "r"(sb + doff),            "l"(Ab1 + (size_t)row * lda + srcoff));
        asm volatile("cp.async.cg.shared.global [%0], [%1], 16;"
                     :: "r"(sb + QPL + doff),      "l"(Ab2 + (size_t)row * lda + srcoff));
        asm volatile("cp.async.cg.shared.global [%0], [%1], 16;"
                     :: "r"(sb + 2 * QPL + doff),  "l"(Bb1 + (size_t)row * K + srcoff));
        asm volatile("cp.async.cg.shared.global [%0], [%1], 16;"
                     :: "r"(sb + 3 * QPL + doff),  "l"(Bb2 + (size_t)row * K + srcoff));
        asm volatile("cp.async.commit_group;");
    };

    #pragma unroll
    for (int s = 0; s < 2; s++) load_stage(s, s);

    const uint32_t lrow = (lane & 15);
    const uint32_t lkb  = (lane >> 4) * 16;

    for (int i = 0; i < NKP; i++) {
        asm volatile("cp.async.wait_group 1;");
        __syncthreads();
        int nxt = i + 2;
        if (nxt < NKP) load_stage(nxt, nxt % 3);
        else           asm volatile("cp.async.commit_group;");

        const uint32_t sb = smem_base + (i % 3) * QSTAGE;
        const uint32_t a1b = sb +            (wm * 64) * QRSB;
        const uint32_t a2b = sb + QPL +      (wm * 64) * QRSB;
        const uint32_t b1b = sb + 2 * QPL +  (wn * 16) * QRSB;
        const uint32_t b2b = sb + 3 * QPL +  (wn * 16) * QRSB;

        #pragma unroll
        for (int ks = 0; ks < 2; ks++) {
            uint32_t B1f[4], B2f[4];
            LDSM_X4(B1f, b1b + lrow * QRSB + ks * 32 + lkb);
            LDSM_X4(B2f, b2b + lrow * QRSB + ks * 32 + lkb);
            #pragma unroll
            for (int mt = 0; mt < 4; mt++) {
                uint32_t A1f[4], A2f[4];
                LDSM_X4(A1f, a1b + (mt * 16 + lrow) * QRSB + ks * 32 + lkb);
                LDSM_X4(A2f, a2b + (mt * 16 + lrow) * QRSB + ks * 32 + lkb);
                #pragma unroll
                for (int nt = 0; nt < 2; nt++) {
                    MMA_S8(acc1[mt][nt], A1f, B1f[nt], B1f[nt + 2]);
                    MMA_S8(accX[mt][nt], A1f, B2f[nt], B2f[nt + 2]);
                    MMA_S8(accX[mt][nt], A2f, B1f[nt], B1f[nt + 2]);
                }
            }
        }
    }
    __syncthreads();

    // combine limbs -> fp32, bounce to smem
    float* stile = (float*)smem;                       // [128][132]
    const int groupID = lane >> 2, tig = lane & 3;
    #pragma unroll
    for (int mt = 0; mt < 4; mt++) {
        int r0 = wm * 64 + mt * 16 + groupID;
        #pragma unroll
        for (int nt = 0; nt < 2; nt++) {
            int c = wn * 16 + nt * 8 + tig * 2;
            stile[r0 * 132 + c]           = (float)acc1[mt][nt][0] + (float)accX[mt][nt][0] * (1.f/256.f);
            stile[r0 * 132 + c + 1]       = (float)acc1[mt][nt][1] + (float)accX[mt][nt][1] * (1.f/256.f);
            stile[(r0 + 8) * 132 + c]     = (float)acc1[mt][nt][2] + (float)accX[mt][nt][2] * (1.f/256.f);
            stile[(r0 + 8) * 132 + c + 1] = (float)acc1[mt][nt][3] + (float)accX[mt][nt][3] * (1.f/256.f);
        }
    }
    __syncthreads();

    // coalesced epilogue with dequant scales
    const int ecol = (tid & 31) * 4;
    const int erow = tid >> 5;
    int col = n0 + ecol;
    float4 sw4 = *(const float4*)(swc + col);
    float4 b4v = make_float4(0.f, 0.f, 0.f, 0.f);
    if (HAS_BIAS) b4v = *(const float4*)(bias + col);

    #pragma unroll
    for (int it = 0; it < 8; it++) {
        int rl = it * 16 + erow;
        int row = m0 + rl;
        float srow = sa[row];
        float4 v = *(float4*)&stile[rl * 132 + ecol];
        v.x = v.x * srow * sw4.x;
        v.y = v.y * srow * sw4.y;
        v.z = v.z * srow * sw4.z;
        v.w = v.w * srow * sw4.w;
        if (HAS_BIAS) { v.x += b4v.x; v.y += b4v.y; v.z += b4v.z; v.w += b4v.w; }
        if (HAS_RES) {
            float4 r4 = *(const float4*)(res + (size_t)row * Nc + col);
            v.x += r4.x; v.y += r4.y; v.z += r4.z; v.w += r4.w;
        }
        *(float4*)(Cf + (size_t)row * Nc + col) = v;
    }
}

// ---------------- chunked scan (== FFT causal conv) ----------------
#define CHUNK 64
#define NCHUNK (SEQ_LEN / CHUNK)

__global__ __launch_bounds__(128) void scan1(const float* __restrict__ proj,
                                             const float* __restrict__ A_log,
                                             float* __restrict__ carry)
{
    int c = blockIdx.x, b = blockIdx.y, s = threadIdx.x;
    float lam = expf(-expf(A_log[s]));
    size_t row0 = (size_t)b * SEQ_LEN + c * CHUNK;
    float y = 0.f;
    #pragma unroll 8
    for (int t = 0; t < CHUNK; t++) {
        const float* p = proj + (row0 + t) * NPROJ;
        y = fmaf(lam, y, p[s] * p[128 + s]);
    }
    carry[(b * NCHUNK + c) * D_STATE + s] = y;
}

__global__ __launch_bounds__(128) void scan2(const float* __restrict__ A_log,
                                             float* __restrict__ carry)
{
    int b = blockIdx.x, s = threadIdx.x;
    float lam64 = expf(-expf(A_log[s]) * (float)CHUNK);
    float S = 0.f;
    for (int c = 0; c < NCHUNK; c++) {
        size_t i = (size_t)(b * NCHUNK + c) * D_STATE + s;
        float f = carry[i];
        carry[i] = S;
        S = fmaf(lam64, S, f);
    }
}

__global__ __launch_bounds__(128) void scan3(const float* __restrict__ proj,
                                             const float* __restrict__ A_log,
                                             const float* __restrict__ carry,
                                             int8_t* __restrict__ y1q,
                                             int8_t* __restrict__ y2q,
                                             float* __restrict__ sy)
{
    __shared__ float wm4[4];
    int c = blockIdx.x, b = blockIdx.y, s = threadIdx.x;
    int wid = s >> 5;
    float lam = expf(-expf(A_log[s]));
    float y = carry[(b * NCHUNK + c) * D_STATE + s];
    size_t row0 = (size_t)b * SEQ_LEN + c * CHUNK;
    for (int t = 0; t < CHUNK; t++) {
        size_t row = row0 + t;
        const float* p = proj + row * NPROJ;
        y = fmaf(lam, y, p[s] * p[128 + s]);
        float o = y * p[256 + s];
        // block max over 128 states
        float m = fabsf(o);
        #pragma unroll
        for (int off = 16; off > 0; off >>= 1)
            m = fmaxf(m, __shfl_xor_sync(0xffffffffu, m, off));
        if ((s & 31) == 0) wm4[wid] = m;
        __syncthreads();
        float bm = fmaxf(fmaxf(wm4[0], wm4[1]), fmaxf(wm4[2], wm4[3]));
        bm = fmaxf(bm, 1e-20f);
        int i1, i2; quant2(o, 127.f / bm, i1, i2);
        y1q[row * D_STATE + s] = (int8_t)i1;
        y2q[row * D_STATE + s] = (int8_t)i2;
        if (s == 0) sy[row] = bm * (1.f / 127.f);
        __syncthreads();
    }
}

// ---------------- launch ----------------
extern "C" void kernel_launch(void* const* d_in, const int* in_sizes, int n_in,
                              void* d_out, int out_size)
{
    const float* x        = (const float*)d_in[0];
    const float* ln_gamma = (const float*)d_in[1];
    const float* ln_beta  = (const float*)d_in[2];
    const float* W_in     = (const float*)d_in[3];
    const float* b_in     = (const float*)d_in[4];
    const float* W_xs     = (const float*)d_in[5];
    const float* W_B      = (const float*)d_in[6];
    const float* b_B      = (const float*)d_in[7];
    const float* W_C      = (const float*)d_in[8];
    const float* b_C      = (const float*)d_in[9];
    const float* A_log    = (const float*)d_in[10];
    const float* Dv       = (const float*)d_in[11];
    const float* W_so     = (const float*)d_in[12];
    const float* W_out    = (const float*)d_in[13];
    const float* b_out    = (const float*)d_in[14];
    float* out = (float*)d_out;

    uint32_t *p_a1, *p_a2;
    int8_t *p_y1, *p_y2, *p_W4q1, *p_W4q2, *p_W3q1, *p_W3q2, *p_W1q1, *p_W1q2;
    __half *p_WinA, *p_WcatA, *p_WpkB, *p_WoutB;
    float *p_sa, *p_sy, *p_proj, *p_W4f, *p_Wcatf;
    float *p_swc4, *p_swc3, *p_swc1, *p_b4, *p_b5, *p_carry;
    cudaGetSymbolAddress((void**)&p_a1,    g_a1);
    cudaGetSymbolAddress((void**)&p_a2,    g_a2);
    cudaGetSymbolAddress((void**)&p_sa,    g_sa);
    cudaGetSymbolAddress((void**)&p_y1,    g_y1);
    cudaGetSymbolAddress((void**)&p_y2,    g_y2);
    cudaGetSymbolAddress((void**)&p_sy,    g_sy);
    cudaGetSymbolAddress((void**)&p_proj,  g_proj);
    cudaGetSymbolAddress((void**)&p_WinA,  g_WinA);
    cudaGetSymbolAddress((void**)&p_WcatA, g_WcatA);
    cudaGetSymbolAddress((void**)&p_WpkB,  g_WpkB);
    cudaGetSymbolAddress((void**)&p_WoutB, g_WoutB);
    cudaGetSymbolAddress((void**)&p_W4f,   g_W4f);
    cudaGetSymbolAddress((void**)&p_Wcatf, g_Wcatf);
    cudaGetSymbolAddress((void**)&p_W4q1,  g_W4q1);
    cudaGetSymbolAddress((void**)&p_W4q2,  g_W4q2);
    cudaGetSymbolAddress((void**)&p_W3q1,  g_W3q1);
    cudaGetSymbolAddress((void**)&p_W3q2,  g_W3q2);
    cudaGetSymbolAddress((void**)&p_W1q1,  g_W1q1);
    cudaGetSymbolAddress((void**)&p_W1q2,  g_W1q2);
    cudaGetSymbolAddress((void**)&p_swc4,  g_swc4);
    cudaGetSymbolAddress((void**)&p_swc3,  g_swc3);
    cudaGetSymbolAddress((void**)&p_swc1,  g_swc1);
    cudaGetSymbolAddress((void**)&p_b4,    g_b4);
    cudaGetSymbolAddress((void**)&p_b5,    g_b5);
    cudaGetSymbolAddress((void**)&p_carry, g_carry);

    cudaFuncSetAttribute(pgemm, cudaFuncAttributeMaxDynamicSharedMemorySize, PGSM);
    cudaFuncSetAttribute(qgemm<true,  false>, cudaFuncAttributeMaxDynamicSharedMemorySize, QGSM);
    cudaFuncSetAttribute(qgemm<true,  true >, cudaFuncAttributeMaxDynamicSharedMemorySize, QGSM);
    cudaFuncSetAttribute(qgemm<false, true >, cudaFuncAttributeMaxDynamicSharedMemorySize, QGSM);

    // ---- weight prep (fp16 splits) ----
    prep_split_A<<<(D_MODEL * D_MODEL + 255) / 256, 256>>>(W_in, p_WinA, D_MODEL, D_MODEL);
    prep_catA<<<(KCAT * D_MODEL + 255) / 256, 256>>>(W_in, Dv, W_so, p_WcatA);
    prep_pkB<<<(NPROJ * D_MODEL + 255) / 256, 256>>>(W_xs, W_B, W_C, p_WpkB);
    prep_outB<<<(D_MODEL * D_MODEL + 255) / 256, 256>>>(W_out, p_WoutB);

    // ---- combined weights (fp32) ----
    pgemm<<<dim3(NPROJ / PBN, D_MODEL / PBM), 256, PGSM>>>(p_WinA,  p_WpkB,  D_MODEL, p_W4f,   D_MODEL);
    pgemm<<<dim3(D_MODEL / PBN, KCAT / PBM), 256, PGSM>>>(p_WcatA, p_WoutB, D_MODEL, p_Wcatf, KCAT);

    // ---- quantize combined weights ----
    quant_w4<<<NPROJ, 128>>>(p_W4f, p_W4q1, p_W4q2, p_swc4);
    quant_wcat<<<D_MODEL, 128>>>(p_Wcatf, p_W3q1, p_W3q2, p_swc3, p_W1q1, p_W1q2, p_swc1);

    // ---- combined biases ----
    bias4_k<<<3, 128>>>(b_in, W_xs, W_B, b_B, W_C, b_C, p_b4);
    bias5_k<<<4, 256>>>(b_in, Dv, W_out, b_out, p_b5);

    // ---- LayerNorm -> int8 limbs ----
    ln_q_kernel<<<ROWS, 256>>>(x, ln_gamma, ln_beta, p_a1, p_a2, p_sa);

    // ---- proj = xn @ W4 + b4 ----
    qgemm<true, false><<<dim3(NPROJ / BN, ROWS / BM), 512, QGSM>>>(
        (const int8_t*)p_a1, (const int8_t*)p_a2, D_MODEL,
        p_W4q1, p_W4q2, D_MODEL, NPROJ, p_sa, p_swc4, p_proj, p_b4, nullptr);

    // ---- chunked linear recurrence (== FFT causal conv) -> ysc int8 limbs ----
    scan1<<<dim3(NCHUNK, BATCH), 128>>>(p_proj, A_log, p_carry);
    scan2<<<BATCH, 128>>>(A_log, p_carry);
    scan3<<<dim3(NCHUNK, BATCH), 128>>>(p_proj, A_log, p_carry, p_y1, p_y2, p_sy);

    // ---- out = xn @ W3 + b5 + x ----
    qgemm<true, true><<<dim3(D_MODEL / BN, ROWS / BM), 512, QGSM>>>(
        (const int8_t*)p_a1, (const int8_t*)p_a2, D_MODEL,
        p_W3q1, p_W3q2, D_MODEL, D_MODEL, p_sa, p_swc3, out, p_b5, x);

    // ---- out += ysc @ W1 ----
    qgemm<false, true><<<dim3(D_MODEL / BN, ROWS / BM), 512, QGSM>>>(
        p_y1, p_y2, D_STATE,
        p_W1q1, p_W1q2, D_STATE, D_MODEL, p_sy, p_swc1, out, nullptr, out);
}

// round 11
// speedup vs baseline: 3.0419x; 3.0419x over previous
#include <cuda_runtime.h>
#include <cuda_fp16.h>
#include <math.h>
#include <stdint.h>

#define D_MODEL 1024
#define D_STATE 128
#define SEQ_LEN 4096
#define BATCH   4
#define ROWS    (BATCH * SEQ_LEN)        // 16384
#define LN_EPS  1e-3f
#define NPROJ   384
#define ACTW    1152                     // [xn(1024) | ysc(128)]
#define KOUT    1152
#define KCAT    1152

// ---------------- scratch (allocation-free: __device__ globals) ----------------
__device__ __half g_act [(size_t)ROWS * ACTW];
__device__ float  g_proj[(size_t)ROWS * NPROJ];
__device__ __half g_WinA [(size_t)D_MODEL * 2 * D_MODEL];
__device__ __half g_WcatA[(size_t)KCAT    * 2 * D_MODEL];
__device__ __half g_WpkB [(size_t)NPROJ   * 2 * D_MODEL];
__device__ __half g_WoutB[(size_t)D_MODEL * 2 * D_MODEL];
__device__ __half g_W4  [(size_t)NPROJ   * 2 * D_MODEL];   // [384][2048], Kb=1024
__device__ __half g_Wcat[(size_t)D_MODEL * 2 * KCAT];      // [1024][2304], Kb=1152
__device__ float g_b4[NPROJ];
__device__ float g_b5[D_MODEL];
__device__ float g_carry[BATCH * 64 * D_STATE];

// ---------------- helpers ----------------
__device__ __forceinline__ uint32_t cvta_smem(const void* p) {
    uint32_t a;
    asm("{ .reg .u64 t; cvta.to.shared.u64 t, %1; cvt.u32.u64 %0, t; }" : "=r"(a) : "l"(p));
    return a;
}
__device__ __forceinline__ uint32_t pack_h2(__half a, __half b) {
    __half2 t; t.x = a; t.y = b;
    return *reinterpret_cast<uint32_t*>(&t);
}

#define MMA_F16(d, a, b) \
    asm volatile( \
        "mma.sync.aligned.m16n8k16.row.col.f32.f16.f16.f32 " \
        "{%0,%1,%2,%3}, {%4,%5,%6,%7}, {%8,%9}, {%0,%1,%2,%3};" \
        : "+f"((d)[0]), "+f"((d)[1]), "+f"((d)[2]), "+f"((d)[3]) \
        : "r"((a)[0]), "r"((a)[1]), "r"((a)[2]), "r"((a)[3]), \
          "r"((b)[0]), "r"((b)[1]))

#define LDSM_X4(r, addr) \
    asm volatile("ldmatrix.sync.aligned.m8n8.x4.shared.b16 {%0,%1,%2,%3}, [%4];" \
        : "=r"((r)[0]), "=r"((r)[1]), "=r"((r)[2]), "=r"((r)[3]) : "r"(addr))

// ---------------- LayerNorm -> fp16 into g_act (stride ACTW) ----------------
__global__ __launch_bounds__(256) void ln_h_kernel(
    const float* __restrict__ x, const float* __restrict__ gamma,
    const float* __restrict__ beta, __half* __restrict__ act)
{
    int row = blockIdx.x;
    int tid = threadIdx.x;
    const float4* xr = (const float4*)(x + (size_t)row * D_MODEL);
    float4 v = xr[tid];

    float s  = v.x + v.y + v.z + v.w;
    float sq = v.x*v.x + v.y*v.y + v.z*v.z + v.w*v.w;
    #pragma unroll
    for (int o = 16; o > 0; o >>= 1) {
        s  += __shfl_xor_sync(0xffffffffu, s,  o);
        sq += __shfl_xor_sync(0xffffffffu, sq, o);
    }
    __shared__ float sh_s[8], sh_q[8];
    int wid = tid >> 5, lid = tid & 31;
    if (lid == 0) { sh_s[wid] = s; sh_q[wid] = sq; }
    __syncthreads();
    if (wid == 0) {
        float a = (lid < 8) ? sh_s[lid] : 0.f;
        float b = (lid < 8) ? sh_q[lid] : 0.f;
        #pragma unroll
        for (int o = 4; o > 0; o >>= 1) {
            a += __shfl_xor_sync(0xffffffffu, a, o);
            b += __shfl_xor_sync(0xffffffffu, b, o);
        }
        if (lid == 0) { sh_s[0] = a; sh_q[0] = b; }
    }
    __syncthreads();
    float mu   = sh_s[0] * (1.0f / D_MODEL);
    float var  = sh_q[0] * (1.0f / D_MODEL) - mu * mu;
    float rstd = rsqrtf(var + LN_EPS);

    float4 gv = ((const float4*)gamma)[tid];
    float4 bv = ((const float4*)beta)[tid];
    float o0 = (v.x - mu) * rstd * gv.x + bv.x;
    float o1 = (v.y - mu) * rstd * gv.y + bv.y;
    float o2 = (v.z - mu) * rstd * gv.z + bv.z;
    float o3 = (v.w - mu) * rstd * gv.w + bv.w;

    uint2 hv = make_uint2(pack_h2(__float2half_rn(o0), __float2half_rn(o1)),
                          pack_h2(__float2half_rn(o2), __float2half_rn(o3)));
    *(uint2*)(act + (size_t)row * ACTW + tid * 4) = hv;
}

// ---------------- merged prep: W4-side (WinA + WpkB) ----------------
__device__ __forceinline__ void split_store(__half* dst, size_t base, int K, int k, float w) {
    __half hi = __float2half_rn(w);
    __half lo = __float2half_rn(w - __half2float(hi));
    dst[base + k]     = hi;
    dst[base + K + k] = lo;
}

#define N_W4PREP (D_MODEL * D_MODEL + 3 * D_MODEL * D_STATE)   // 1441792
__global__ void prep_w4_side(const float* __restrict__ W_in,
                             const float* __restrict__ Wxs, const float* __restrict__ WB,
                             const float* __restrict__ WC,
                             __half* __restrict__ WinA, __half* __restrict__ WpkB)
{
    int idx = blockIdx.x * blockDim.x + threadIdx.x;
    if (idx < D_MODEL * D_MODEL) {
        int m = idx >> 10, k = idx & 1023;
        split_store(WinA, (size_t)m * 2 * D_MODEL, D_MODEL, k, W_in[idx]);
    } else if (idx < N_W4PREP) {
        int r = idx - D_MODEL * D_MODEL;            // 0..393215 over [j(1024) x n(384)]
        int j = r / NPROJ, n = r % NPROJ;
        float w;
        if (n < 128)      w = Wxs[(size_t)j * 128 + n];
        else if (n < 256) w = WB [(size_t)j * 128 + (n - 128)];
        else              w = WC [(size_t)j * 128 + (n - 256)];
        split_store(WpkB, (size_t)n * 2 * D_MODEL, D_MODEL, j, w);
    }
}

// ---------------- merged prep: Wcat-side (WcatA + WoutB) ----------------
#define N_WCATPREP (KCAT * D_MODEL + D_MODEL * D_MODEL)        // 2228224
__global__ void prep_wcat_side(const float* __restrict__ W_in, const float* __restrict__ D,
                               const float* __restrict__ W_so, const float* __restrict__ W_out,
                               __half* __restrict__ WcatA, __half* __restrict__ WoutB)
{
    int idx = blockIdx.x * blockDim.x + threadIdx.x;
    if (idx < KCAT * D_MODEL) {
        int m = idx >> 10, j = idx & 1023;
        float w = (m < D_MODEL) ? (W_in[(size_t)m * D_MODEL + j] * D[j])
                                : W_so[(size_t)(m - D_MODEL) * D_MODEL + j];
        split_store(WcatA, (size_t)m * 2 * D_MODEL, D_MODEL, j, w);
    } else if (idx < N_WCATPREP) {
        int r = idx - KCAT * D_MODEL;
        int j = r >> 10, n = r & 1023;
        split_store(WoutB, (size_t)n * 2 * D_MODEL, D_MODEL, j, W_out[r]);
    }
}

// ---------------- bias reductions (block per output) ----------------
__global__ __launch_bounds__(128) void bias4_k(const float* __restrict__ b_in,
                        const float* __restrict__ W_xs, const float* __restrict__ W_B,
                        const float* __restrict__ bB,  const float* __restrict__ W_C,
                        const float* __restrict__ bC,  float* __restrict__ b4)
{
    __shared__ float sh[4];
    int n = blockIdx.x, tid = threadIdx.x;
    const float* W; const float* badd = nullptr; int c = n;
    if (n < 128)      { W = W_xs; }
    else if (n < 256) { W = W_B; c = n - 128; badd = bB; }
    else              { W = W_C; c = n - 256; badd = bC; }
    float acc = 0.f;
    for (int j = tid; j < D_MODEL; j += 128) acc += b_in[j] * W[(size_t)j * 128 + c];
    #pragma unroll
    for (int o = 16; o > 0; o >>= 1) acc += __shfl_xor_sync(0xffffffffu, acc, o);
    if ((tid & 31) == 0) sh[tid >> 5] = acc;
    __syncthreads();
    if (tid == 0) {
        float t = sh[0] + sh[1] + sh[2] + sh[3];
        b4[n] = t + (badd ? badd[c] : 0.f);
    }
}

__global__ __launch_bounds__(128) void bias5_k(const float* __restrict__ b_in,
                        const float* __restrict__ D, const float* __restrict__ W_out,
                        const float* __restrict__ b_out, float* __restrict__ b5)
{
    __shared__ float sh[4];
    int n = blockIdx.x, tid = threadIdx.x;
    float acc = 0.f;
    for (int j = tid; j < D_MODEL; j += 128)
        acc += b_in[j] * D[j] * W_out[(size_t)j * D_MODEL + n];
    #pragma unroll
    for (int o = 16; o > 0; o >>= 1) acc += __shfl_xor_sync(0xffffffffu, acc, o);
    if ((tid & 31) == 0) sh[tid >> 5] = acc;
    __syncthreads();
    if (tid == 0) b5[n] = sh[0] + sh[1] + sh[2] + sh[3] + b_out[n];
}

// ---------------- precompute GEMM (3-term fp16 dual split -> split fp16 Wbig) ----------------
#define PBM 128
#define PBN 64
#define PRSB 80
#define PTILEA (PBM * PRSB)
#define PSTAGE ((PBM + PBN) * PRSB)
#define PGSM (3 * PSTAGE)

__global__ __launch_bounds__(256, 2)
void pgemm(const __half* __restrict__ A, const __half* __restrict__ B, int K,
           __half* __restrict__ Wbig, int Kb, int colOff)
{
    extern __shared__ __align__(128) char smem[];
    const int tid  = threadIdx.x;
    const int warp = tid >> 5, lane = tid & 31;
    const int wm = warp & 1, wn = warp >> 1;
    const int m0 = blockIdx.y * PBM, n0 = blockIdx.x * PBN;
    const uint32_t smem_base = cvta_smem(smem);

    const int KB = K / 32;
    const int NK = 3 * KB;
    const size_t row_bytes = (size_t)K * 4;          // 2K fp16
    const __half* Ab = A + (size_t)m0 * 2 * K;
    const __half* Bb = B + (size_t)n0 * 2 * K;

    float acc[4][2][4];
    #pragma unroll
    for (int i = 0; i < 4; i++)
        #pragma unroll
        for (int j = 0; j < 2; j++)
            #pragma unroll
            for (int e = 0; e < 4; e++) acc[i][j][e] = 0.f;

    auto load_stage = [&](int sk, int buf) {
        const uint32_t sb = smem_base + buf * PSTAGE;
        int lkA = (sk < 2 * KB) ? sk : sk - 2 * KB;   // A: [hi|lo|hi]
        int lkB = (sk < KB)     ? sk : sk - KB;       // B: [hi|hi|lo]
        const size_t kbA = (size_t)lkA * 64;
        const size_t kbB = (size_t)lkB * 64;
        #pragma unroll
        for (int j = 0; j < 2; j++) {
            int chunk = tid + j * 256;
            int row = chunk >> 2, cb = chunk & 3;
            const char* ga = (const char*)Ab + (size_t)row * row_bytes + kbA + cb * 16;
            asm volatile("cp.async.cg.shared.global [%0], [%1], 16;"
                         :: "r"(sb + row * PRSB + cb * 16), "l"(ga));
        }
        {
            int row = tid >> 2, cb = tid & 3;
            const char* gb = (const char*)Bb + (size_t)row * row_bytes + kbB + cb * 16;
            asm volatile("cp.async.cg.shared.global [%0], [%1], 16;"
                         :: "r"(sb + PTILEA + row * PRSB + cb * 16), "l"(gb));
        }
        asm volatile("cp.async.commit_group;");
    };

    #pragma unroll
    for (int s = 0; s < 2; s++) load_stage(s, s);

    const uint32_t lrow = (lane & 15);
    const uint32_t lkb  = (lane >> 4) * 16;

    for (int i = 0; i < NK; i++) {
        asm volatile("cp.async.wait_group 1;");
        __syncthreads();
        int nxt = i + 2;
        if (nxt < NK) load_stage(nxt, nxt % 3);
        else          asm volatile("cp.async.commit_group;");

        const uint32_t sb = smem_base + (i % 3) * PSTAGE;
        const uint32_t abase = sb + (wm * 64) * PRSB;
        const uint32_t bbase = sb + PTILEA + (wn * 16) * PRSB;

        #pragma unroll
        for (int ks = 0; ks < 2; ks++) {
            uint32_t Af[4][4], Bf[4];
            #pragma unroll
            for (int mt = 0; mt < 4; mt++)
                LDSM_X4(Af[mt], abase + (mt * 16 + lrow) * PRSB + ks * 32 + lkb);
            LDSM_X4(Bf, bbase + lrow * PRSB + ks * 32 + lkb);

            #pragma unroll
            for (int mt = 0; mt < 4; mt++) {
                #pragma unroll
                for (int nt = 0; nt < 2; nt++) {
                    uint32_t b2[2] = { Bf[nt], Bf[nt + 2] };
                    MMA_F16(acc[mt][nt], Af[mt], b2);
                }
            }
        }
    }

    // transposed split scatter: Wbig[n][colOff + k] = hi, [Kb + colOff + k] = lo
    const int groupID = lane >> 2, tig = lane & 3;
    #pragma unroll
    for (int mt = 0; mt < 4; mt++) {
        #pragma unroll
        for (int nt = 0; nt < 2; nt++) {
            int r0 = m0 + wm * 64 + mt * 16 + groupID;
            int c0 = n0 + wn * 16 + nt * 8 + tig * 2;
            #pragma unroll
            for (int e = 0; e < 4; e++) {
                int r = r0 + (e >> 1) * 8;
                int c = c0 + (e & 1);
                float v = acc[mt][nt][e];
                __half hi = __float2half_rn(v);
                __half lo = __float2half_rn(v - __half2float(hi));
                size_t base = (size_t)c * 2 * Kb + colOff + r;
                Wbig[base]      = hi;
                Wbig[base + Kb] = lo;
            }
        }
    }
}

// ---------------- big GEMM: C[M,Nc] = A_fp16[M,K](lda) @ (W_hi+W_lo)[Nc,2K]^T ----------------
#define BM 128
#define BN 128
#define RSB 80
#define TILE_B (BM * RSB)
#define STAGE  (3 * TILE_B)
#define GSM    (3 * STAGE)                       // 92160

template<bool HAS_BIAS, bool HAS_RES>
__global__ __launch_bounds__(256, 2)
void bgemm(const __half* __restrict__ A, int lda, const __half* __restrict__ Bw,
           int K, int Nc, float* __restrict__ Cf,
           const float* __restrict__ bias, const float* __restrict__ res)
{
    extern __shared__ __align__(128) char smem[];
    const int tid  = threadIdx.x;
    const int warp = tid >> 5, lane = tid & 31;
    const int wm = warp & 1, wn = warp >> 1;
    const int m0 = blockIdx.y * BM, n0 = blockIdx.x * BN;
    const uint32_t smem_base = cvta_smem(smem);

    const int NKP = K / 32;
    const size_t arow_bytes = (size_t)lda * 2;
    const size_t brow_bytes = (size_t)K * 4;
    const size_t lo_off     = (size_t)K * 2;
    const __half* Ab = A  + (size_t)m0 * lda;
    const __half* Bb = Bw + (size_t)n0 * 2 * K;

    float acc[4][4][4];
    #pragma unroll
    for (int i = 0; i < 4; i++)
        #pragma unroll
        for (int j = 0; j < 4; j++)
            #pragma unroll
            for (int e = 0; e < 4; e++) acc[i][j][e] = 0.f;

    auto load_stage = [&](int sk, int buf) {
        const uint32_t sb = smem_base + buf * STAGE;
        const size_t kb = (size_t)sk * 64;
        #pragma unroll
        for (int j = 0; j < 2; j++) {
            int chunk = tid + j * 256;
            int row = chunk >> 2, cb = chunk & 3;
            const char* ga = (const char*)Ab + (size_t)row * arow_bytes + kb + cb * 16;
            asm volatile("cp.async.cg.shared.global [%0], [%1], 16;"
                         :: "r"(sb + row * RSB + cb * 16), "l"(ga));
        }
        #pragma unroll
        for (int j = 0; j < 2; j++) {
            int chunk = tid + j * 256;
            int row = chunk >> 2, cb = chunk & 3;
            const char* gh = (const char*)Bb + (size_t)row * brow_bytes + kb + cb * 16;
            asm volatile("cp.async.cg.shared.global [%0], [%1], 16;"
                         :: "r"(sb + TILE_B + row * RSB + cb * 16), "l"(gh));
        }
        #pragma unroll
        for (int j = 0; j < 2; j++) {
            int chunk = tid + j * 256;
            int row = chunk >> 2, cb = chunk & 3;
            const char* gl = (const char*)Bb + (size_t)row * brow_bytes + lo_off + kb + cb * 16;
            asm volatile("cp.async.cg.shared.global [%0], [%1], 16;"
                         :: "r"(sb + 2 * TILE_B + row * RSB + cb * 16), "l"(gl));
        }
        asm volatile("cp.async.commit_group;");
    };

    #pragma unroll
    for (int s = 0; s < 2; s++) load_stage(s, s);

    const uint32_t lrow = (lane & 15);
    const uint32_t lkb  = (lane >> 4) * 16;

    for (int i = 0; i < NKP; i++) {
        asm volatile("cp.async.wait_group 1;");
        __syncthreads();
        int nxt = i + 2;
        if (nxt < NKP) load_stage(nxt, nxt % 3);
        else           asm volatile("cp.async.commit_group;");

        const uint32_t sb = smem_base + (i % 3) * STAGE;
        const uint32_t abase  = sb + (wm * 64) * RSB;
        const uint32_t bhbase = sb + TILE_B     + (wn * 32) * RSB;
        const uint32_t blbase = sb + 2 * TILE_B + (wn * 32) * RSB;

        #pragma unroll
        for (int ks = 0; ks < 2; ks++) {
            uint32_t Af[4][4], Bh[2][4], Bl[2][4];
            #pragma unroll
            for (int mt = 0; mt < 4; mt++)
                LDSM_X4(Af[mt], abase + (mt * 16 + lrow) * RSB + ks * 32 + lkb);
            #pragma unroll
            for (int g = 0; g < 2; g++)
                LDSM_X4(Bh[g], bhbase + (g * 16 + lrow) * RSB + ks * 32 + lkb);
            #pragma unroll
            for (int g = 0; g < 2; g++)
                LDSM_X4(Bl[g], blbase + (g * 16 + lrow) * RSB + ks * 32 + lkb);

            #pragma unroll
            for (int mt = 0; mt < 4; mt++)
                #pragma unroll
                for (int nt = 0; nt < 4; nt++) {
                    uint32_t b2[2] = { Bh[nt >> 1][nt & 1], Bh[nt >> 1][(nt & 1) + 2] };
                    MMA_F16(acc[mt][nt], Af[mt], b2);
                }
            #pragma unroll
            for (int mt = 0; mt < 4; mt++)
                #pragma unroll
                for (int nt = 0; nt < 4; nt++) {
                    uint32_t b2[2] = { Bl[nt >> 1][nt & 1], Bl[nt >> 1][(nt & 1) + 2] };
                    MMA_F16(acc[mt][nt], Af[mt], b2);
                }
        }
    }
    __syncthreads();

    // ---- acc -> smem bounce -> fused coalesced epilogue ----
    float* stile = (float*)smem;               // [128][132]
    const int groupID = lane >> 2, tig = lane & 3;
    #pragma unroll
    for (int mt = 0; mt < 4; mt++) {
        int r0 = wm * 64 + mt * 16 + groupID;
        #pragma unroll
        for (int nt = 0; nt < 4; nt++) {
            int c = wn * 32 + nt * 8 + tig * 2;
            *(float2*)&stile[r0 * 132 + c]       = make_float2(acc[mt][nt][0], acc[mt][nt][1]);
            *(float2*)&stile[(r0 + 8) * 132 + c] = make_float2(acc[mt][nt][2], acc[mt][nt][3]);
        }
    }
    __syncthreads();

    float4 b4 = make_float4(0.f, 0.f, 0.f, 0.f);
    int col = n0 + lane * 4;
    if (HAS_BIAS) b4 = *(const float4*)(bias + col);

    #pragma unroll 4
    for (int rr = 0; rr < 16; rr++) {
        int r = warp * 16 + rr;
        int row = m0 + r;
        float4 v = *(float4*)&stile[r * 132 + lane * 4];
        if (HAS_BIAS) { v.x += b4.x; v.y += b4.y; v.z += b4.z; v.w += b4.w; }
        if (HAS_RES) {
            float4 r4 = *(const float4*)(res + (size_t)row * Nc + col);
            v.x += r4.x; v.y += r4.y; v.z += r4.z; v.w += r4.w;
        }
        *(float4*)(Cf + (size_t)row * Nc + col) = v;
    }
}

// ---------------- chunked scan (== FFT causal conv) ----------------
#define CHUNK 64
#define NCHUNK (SEQ_LEN / CHUNK)

__global__ __launch_bounds__(128) void scan1(const float* __restrict__ proj,
                                             const float* __restrict__ A_log,
                                             float* __restrict__ carry)
{
    int c = blockIdx.x, b = blockIdx.y, s = threadIdx.x;
    float lam = expf(-expf(A_log[s]));
    size_t row0 = (size_t)b * SEQ_LEN + c * CHUNK;
    float y = 0.f;
    #pragma unroll 8
    for (int t = 0; t < CHUNK; t++) {
        const float* p = proj + (row0 + t) * NPROJ;
        y = fmaf(lam, y, p[s] * p[128 + s]);
    }
    carry[(b * NCHUNK + c) * D_STATE + s] = y;
}

__global__ __launch_bounds__(128) void scan2(const float* __restrict__ A_log,
                                             float* __restrict__ carry)
{
    int b = blockIdx.x, s = threadIdx.x;
    float lam64 = expf(-expf(A_log[s]) * (float)CHUNK);
    float S = 0.f;
    for (int c = 0; c < NCHUNK; c++) {
        size_t i = (size_t)(b * NCHUNK + c) * D_STATE + s;
        float f = carry[i];
        carry[i] = S;
        S = fmaf(lam64, S, f);
    }
}

__global__ __launch_bounds__(128) void scan3(const float* __restrict__ proj,
                                             const float* __restrict__ A_log,
                                             const float* __restrict__ carry,
                                             __half* __restrict__ act)
{
    int c = blockIdx.x, b = blockIdx.y, s = threadIdx.x;
    float lam = expf(-expf(A_log[s]));
    float y = carry[(b * NCHUNK + c) * D_STATE + s];
    size_t row0 = (size_t)b * SEQ_LEN + c * CHUNK;
    #pragma unroll 4
    for (int t = 0; t < CHUNK; t++) {
        size_t row = row0 + t;
        const float* p = proj + row * NPROJ;
        y = fmaf(lam, y, p[s] * p[128 + s]);
        act[row * ACTW + D_MODEL + s] = __float2half_rn(y * p[256 + s]);
    }
}

// ---------------- launch ----------------
extern "C" void kernel_launch(void* const* d_in, const int* in_sizes, int n_in,
                              void* d_out, int out_size)
{
    const float* x        = (const float*)d_in[0];
    const float* ln_gamma = (const float*)d_in[1];
    const float* ln_beta  = (const float*)d_in[2];
    const float* W_in     = (const float*)d_in[3];
    const float* b_in     = (const float*)d_in[4];
    const float* W_xs     = (const float*)d_in[5];
    const float* W_B      = (const float*)d_in[6];
    const float* b_B      = (const float*)d_in[7];
    const float* W_C      = (const float*)d_in[8];
    const float* b_C      = (const float*)d_in[9];
    const float* A_log    = (const float*)d_in[10];
    const float* Dv       = (const float*)d_in[11];
    const float* W_so     = (const float*)d_in[12];
    const float* W_out    = (const float*)d_in[13];
    const float* b_out    = (const float*)d_in[14];
    float* out = (float*)d_out;

    __half *p_act, *p_WinA, *p_WcatA, *p_WpkB, *p_WoutB, *p_W4, *p_Wcat;
    float *p_proj, *p_b4, *p_b5, *p_carry;
    cudaGetSymbolAddress((void**)&p_act,   g_act);
    cudaGetSymbolAddress((void**)&p_proj,  g_proj);
    cudaGetSymbolAddress((void**)&p_WinA,  g_WinA);
    cudaGetSymbolAddress((void**)&p_WcatA, g_WcatA);
    cudaGetSymbolAddress((void**)&p_WpkB,  g_WpkB);
    cudaGetSymbolAddress((void**)&p_WoutB, g_WoutB);
    cudaGetSymbolAddress((void**)&p_W4,    g_W4);
    cudaGetSymbolAddress((void**)&p_Wcat,  g_Wcat);
    cudaGetSymbolAddress((void**)&p_b4,    g_b4);
    cudaGetSymbolAddress((void**)&p_b5,    g_b5);
    cudaGetSymbolAddress((void**)&p_carry, g_carry);

    cudaFuncSetAttribute(pgemm, cudaFuncAttributeMaxDynamicSharedMemorySize, PGSM);
    cudaFuncSetAttribute(bgemm<true, false>, cudaFuncAttributeMaxDynamicSharedMemorySize, GSM);
    cudaFuncSetAttribute(bgemm<true, true >, cudaFuncAttributeMaxDynamicSharedMemorySize, GSM);

    // ---- stream fork: precompute off the critical path ----
    cudaStream_t s2, s3;
    cudaStreamCreate(&s2);
    cudaStreamCreate(&s3);
    cudaEvent_t ev0, ev2, ev3;
    cudaEventCreateWithFlags(&ev0, cudaEventDisableTiming);
    cudaEventCreateWithFlags(&ev2, cudaEventDisableTiming);
    cudaEventCreateWithFlags(&ev3, cudaEventDisableTiming);

    cudaEventRecord(ev0, 0);
    cudaStreamWaitEvent(s2, ev0, 0);
    cudaStreamWaitEvent(s3, ev0, 0);

    // s2: W4 chain (needed before proj GEMM)
    prep_w4_side<<<(N_W4PREP + 255) / 256, 256, 0, s2>>>(W_in, W_xs, W_B, W_C, p_WinA, p_WpkB);
    pgemm<<<dim3(NPROJ / PBN, D_MODEL / PBM), 256, PGSM, s2>>>(p_WinA, p_WpkB, D_MODEL, p_W4, D_MODEL, 0);
    bias4_k<<<NPROJ, 128, 0, s2>>>(b_in, W_xs, W_B, b_B, W_C, b_C, p_b4);
    cudaEventRecord(ev2, s2);

    // s3: Wcat chain (needed before out GEMM)
    prep_wcat_side<<<(N_WCATPREP + 255) / 256, 256, 0, s3>>>(W_in, Dv, W_so, W_out, p_WcatA, p_WoutB);
    pgemm<<<dim3(D_MODEL / PBN, KCAT / PBM), 256, PGSM, s3>>>(p_WcatA, p_WoutB, D_MODEL, p_Wcat, KCAT, 0);
    bias5_k<<<D_MODEL, 128, 0, s3>>>(b_in, Dv, W_out, b_out, p_b5);
    cudaEventRecord(ev3, s3);

    // main: LayerNorm -> act[:, 0:1024]
    ln_h_kernel<<<ROWS, 256>>>(x, ln_gamma, ln_beta, p_act);

    // join W4 chain, then proj = xn @ W4 + b4
    cudaStreamWaitEvent(0, ev2, 0);
    bgemm<true, false><<<dim3(NPROJ / BN, ROWS / BM), 256, GSM>>>(
        p_act, ACTW, p_W4, D_MODEL, NPROJ, p_proj, p_b4, nullptr);

    // chunked linear recurrence (== FFT causal conv) -> act[:, 1024:1152]
    scan1<<<dim3(NCHUNK, BATCH), 128>>>(p_proj, A_log, p_carry);
    scan2<<<BATCH, 128>>>(A_log, p_carry);
    scan3<<<dim3(NCHUNK, BATCH), 128>>>(p_proj, A_log, p_carry, p_act);

    // join Wcat chain, then out = [xn | ysc] @ Wcat + b5 + x
    cudaStreamWaitEvent(0, ev3, 0);
    bgemm<true, true><<<dim3(D_MODEL / BN, ROWS / BM), 256, GSM>>>(
        p_act, ACTW, p_Wcat, KOUT, D_MODEL, out, p_b5, x);

    cudaEventDestroy(ev0);
    cudaEventDestroy(ev2);
    cudaEventDestroy(ev3);
    cudaStreamDestroy(s2);
    cudaStreamDestroy(s3);
}

// round 13
// speedup vs baseline: 4.2302x; 1.3906x over previous
#include <cuda_runtime.h>
#include <cuda_fp16.h>
#include <math.h>
#include <stdint.h>

#define D_MODEL 1024
#define D_STATE 128
#define SEQ_LEN 4096
#define BATCH   4
#define ROWS    (BATCH * SEQ_LEN)        // 16384
#define LN_EPS  1e-3f
#define NPROJ   384
#define ACTW    1152                     // [xn(1024) | ysc(128)]
#define KOUT    1152
#define KCAT    1152

// ---------------- scratch (allocation-free: __device__ globals) ----------------
__device__ __half g_act [(size_t)ROWS * ACTW];
__device__ float  g_proj[(size_t)ROWS * NPROJ];
__device__ __half g_WinA [(size_t)D_MODEL * 2 * D_MODEL];
__device__ __half g_WcatA[(size_t)KCAT    * 2 * D_MODEL];
__device__ __half g_WpkB [(size_t)NPROJ   * 2 * D_MODEL];
__device__ __half g_WoutB[(size_t)D_MODEL * 2 * D_MODEL];
__device__ __half g_W4  [(size_t)NPROJ   * D_MODEL];       // [384][1024] fp16
__device__ __half g_Wcat[(size_t)D_MODEL * KCAT];          // [1024][1152] fp16
__device__ float g_b4[NPROJ];
__device__ float g_b5[D_MODEL];
__device__ float g_carry[BATCH * 64 * D_STATE];

// ---------------- helpers ----------------
__device__ __forceinline__ uint32_t cvta_smem(const void* p) {
    uint32_t a;
    asm("{ .reg .u64 t; cvta.to.shared.u64 t, %1; cvt.u32.u64 %0, t; }" : "=r"(a) : "l"(p));
    return a;
}
__device__ __forceinline__ uint32_t pack_h2(__half a, __half b) {
    __half2 t; t.x = a; t.y = b;
    return *reinterpret_cast<uint32_t*>(&t);
}

#define MMA_F16(d, a, b) \
    asm volatile( \
        "mma.sync.aligned.m16n8k16.row.col.f32.f16.f16.f32 " \
        "{%0,%1,%2,%3}, {%4,%5,%6,%7}, {%8,%9}, {%0,%1,%2,%3};" \
        : "+f"((d)[0]), "+f"((d)[1]), "+f"((d)[2]), "+f"((d)[3]) \
        : "r"((a)[0]), "r"((a)[1]), "r"((a)[2]), "r"((a)[3]), \
          "r"((b)[0]), "r"((b)[1]))

#define LDSM_X4(r, addr) \
    asm volatile("ldmatrix.sync.aligned.m8n8.x4.shared.b16 {%0,%1,%2,%3}, [%4];" \
        : "=r"((r)[0]), "=r"((r)[1]), "=r"((r)[2]), "=r"((r)[3]) : "r"(addr))

// ---------------- LayerNorm -> fp16 into g_act (stride ACTW) ----------------
__global__ __launch_bounds__(256) void ln_h_kernel(
    const float* __restrict__ x, const float* __restrict__ gamma,
    const float* __restrict__ beta, __half* __restrict__ act)
{
    int row = blockIdx.x;
    int tid = threadIdx.x;
    const float4* xr = (const float4*)(x + (size_t)row * D_MODEL);
    float4 v = xr[tid];

    float s  = v.x + v.y + v.z + v.w;
    float sq = v.x*v.x + v.y*v.y + v.z*v.z + v.w*v.w;
    #pragma unroll
    for (int o = 16; o > 0; o >>= 1) {
        s  += __shfl_xor_sync(0xffffffffu, s,  o);
        sq += __shfl_xor_sync(0xffffffffu, sq, o);
    }
    __shared__ float sh_s[8], sh_q[8];
    int wid = tid >> 5, lid = tid & 31;
    if (lid == 0) { sh_s[wid] = s; sh_q[wid] = sq; }
    __syncthreads();
    if (wid == 0) {
        float a = (lid < 8) ? sh_s[lid] : 0.f;
        float b = (lid < 8) ? sh_q[lid] : 0.f;
        #pragma unroll
        for (int o = 4; o > 0; o >>= 1) {
            a += __shfl_xor_sync(0xffffffffu, a, o);
            b += __shfl_xor_sync(0xffffffffu, b, o);
        }
        if (lid == 0) { sh_s[0] = a; sh_q[0] = b; }
    }
    __syncthreads();
    float mu   = sh_s[0] * (1.0f / D_MODEL);
    float var  = sh_q[0] * (1.0f / D_MODEL) - mu * mu;
    float rstd = rsqrtf(var + LN_EPS);

    float4 gv = ((const float4*)gamma)[tid];
    float4 bv = ((const float4*)beta)[tid];
    float o0 = (v.x - mu) * rstd * gv.x + bv.x;
    float o1 = (v.y - mu) * rstd * gv.y + bv.y;
    float o2 = (v.z - mu) * rstd * gv.z + bv.z;
    float o3 = (v.w - mu) * rstd * gv.w + bv.w;

    uint2 hv = make_uint2(pack_h2(__float2half_rn(o0), __float2half_rn(o1)),
                          pack_h2(__float2half_rn(o2), __float2half_rn(o3)));
    *(uint2*)(act + (size_t)row * ACTW + tid * 4) = hv;
}

// ---------------- merged prep: W4-side (WinA + WpkB) ----------------
__device__ __forceinline__ void split_store(__half* dst, size_t base, int K, int k, float w) {
    __half hi = __float2half_rn(w);
    __half lo = __float2half_rn(w - __half2float(hi));
    dst[base + k]     = hi;
    dst[base + K + k] = lo;
}

#define N_W4PREP (D_MODEL * D_MODEL + 3 * D_MODEL * D_STATE)   // 1441792
__global__ void prep_w4_side(const float* __restrict__ W_in,
                             const float* __restrict__ Wxs, const float* __restrict__ WB,
                             const float* __restrict__ WC,
                             __half* __restrict__ WinA, __half* __restrict__ WpkB)
{
    int idx = blockIdx.x * blockDim.x + threadIdx.x;
    if (idx < D_MODEL * D_MODEL) {
        int m = idx >> 10, k = idx & 1023;
        split_store(WinA, (size_t)m * 2 * D_MODEL, D_MODEL, k, W_in[idx]);
    } else if (idx < N_W4PREP) {
        int r = idx - D_MODEL * D_MODEL;
        int j = r / NPROJ, n = r % NPROJ;
        float w;
        if (n < 128)      w = Wxs[(size_t)j * 128 + n];
        else if (n < 256) w = WB [(size_t)j * 128 + (n - 128)];
        else              w = WC [(size_t)j * 128 + (n - 256)];
        split_store(WpkB, (size_t)n * 2 * D_MODEL, D_MODEL, j, w);
    }
}

// ---------------- merged prep: Wcat-side (WcatA + WoutB) ----------------
#define N_WCATPREP (KCAT * D_MODEL + D_MODEL * D_MODEL)        // 2228224
__global__ void prep_wcat_side(const float* __restrict__ W_in, const float* __restrict__ D,
                               const float* __restrict__ W_so, const float* __restrict__ W_out,
                               __half* __restrict__ WcatA, __half* __restrict__ WoutB)
{
    int idx = blockIdx.x * blockDim.x + threadIdx.x;
    if (idx < KCAT * D_MODEL) {
        int m = idx >> 10, j = idx & 1023;
        float w = (m < D_MODEL) ? (W_in[(size_t)m * D_MODEL + j] * D[j])
                                : W_so[(size_t)(m - D_MODEL) * D_MODEL + j];
        split_store(WcatA, (size_t)m * 2 * D_MODEL, D_MODEL, j, w);
    } else if (idx < N_WCATPREP) {
        int r = idx - KCAT * D_MODEL;
        int j = r >> 10, n = r & 1023;
        split_store(WoutB, (size_t)n * 2 * D_MODEL, D_MODEL, j, W_out[r]);
    }
}

// ---------------- bias reductions (block per output) ----------------
__global__ __launch_bounds__(128) void bias4_k(const float* __restrict__ b_in,
                        const float* __restrict__ W_xs, const float* __restrict__ W_B,
                        const float* __restrict__ bB,  const float* __restrict__ W_C,
                        const float* __restrict__ bC,  float* __restrict__ b4)
{
    __shared__ float sh[4];
    int n = blockIdx.x, tid = threadIdx.x;
    const float* W; const float* badd = nullptr; int c = n;
    if (n < 128)      { W = W_xs; }
    else if (n < 256) { W = W_B; c = n - 128; badd = bB; }
    else              { W = W_C; c = n - 256; badd = bC; }
    float acc = 0.f;
    for (int j = tid; j < D_MODEL; j += 128) acc += b_in[j] * W[(size_t)j * 128 + c];
    #pragma unroll
    for (int o = 16; o > 0; o >>= 1) acc += __shfl_xor_sync(0xffffffffu, acc, o);
    if ((tid & 31) == 0) sh[tid >> 5] = acc;
    __syncthreads();
    if (tid == 0) {
        float t = sh[0] + sh[1] + sh[2] + sh[3];
        b4[n] = t + (badd ? badd[c] : 0.f);
    }
}

__global__ __launch_bounds__(128) void bias5_k(const float* __restrict__ b_in,
                        const float* __restrict__ D, const float* __restrict__ W_out,
                        const float* __restrict__ b_out, float* __restrict__ b5)
{
    __shared__ float sh[4];
    int n = blockIdx.x, tid = threadIdx.x;
    float acc = 0.f;
    for (int j = tid; j < D_MODEL; j += 128)
        acc += b_in[j] * D[j] * W_out[(size_t)j * D_MODEL + n];
    #pragma unroll
    for (int o = 16; o > 0; o >>= 1) acc += __shfl_xor_sync(0xffffffffu, acc, o);
    if ((tid & 31) == 0) sh[tid >> 5] = acc;
    __syncthreads();
    if (tid == 0) b5[n] = sh[0] + sh[1] + sh[2] + sh[3] + b_out[n];
}

// ---------------- precompute GEMM (3-term fp16 dual split -> fp16 hi Wbig) ----------------
#define PBM 128
#define PBN 64
#define PRSB 80
#define PTILEA (PBM * PRSB)
#define PSTAGE ((PBM + PBN) * PRSB)
#define PGSM (3 * PSTAGE)

__global__ __launch_bounds__(256, 2)
void pgemm(const __half* __restrict__ A, const __half* __restrict__ B, int K,
           __half* __restrict__ Wbig, int Kb, int colOff)
{
    extern __shared__ __align__(128) char smem[];
    const int tid  = threadIdx.x;
    const int warp = tid >> 5, lane = tid & 31;
    const int wm = warp & 1, wn = warp >> 1;
    const int m0 = blockIdx.y * PBM, n0 = blockIdx.x * PBN;
    const uint32_t smem_base = cvta_smem(smem);

    const int KB = K / 32;
    const int NK = 3 * KB;
    const size_t row_bytes = (size_t)K * 4;
    const __half* Ab = A + (size_t)m0 * 2 * K;
    const __half* Bb = B + (size_t)n0 * 2 * K;

    float acc[4][2][4];
    #pragma unroll
    for (int i = 0; i < 4; i++)
        #pragma unroll
        for (int j = 0; j < 2; j++)
            #pragma unroll
            for (int e = 0; e < 4; e++) acc[i][j][e] = 0.f;

    auto load_stage = [&](int sk, int buf) {
        const uint32_t sb = smem_base + buf * PSTAGE;
        int lkA = (sk < 2 * KB) ? sk : sk - 2 * KB;   // A: [hi|lo|hi]
        int lkB = (sk < KB)     ? sk : sk - KB;       // B: [hi|hi|lo]
        const size_t kbA = (size_t)lkA * 64;
        const size_t kbB = (size_t)lkB * 64;
        #pragma unroll
        for (int j = 0; j < 2; j++) {
            int chunk = tid + j * 256;
            int row = chunk >> 2, cb = chunk & 3;
            const char* ga = (const char*)Ab + (size_t)row * row_bytes + kbA + cb * 16;
            asm volatile("cp.async.cg.shared.global [%0], [%1], 16;"
                         :: "r"(sb + row * PRSB + cb * 16), "l"(ga));
        }
        {
            int row = tid >> 2, cb = tid & 3;
            const char* gb = (const char*)Bb + (size_t)row * row_bytes + kbB + cb * 16;
            asm volatile("cp.async.cg.shared.global [%0], [%1], 16;"
                         :: "r"(sb + PTILEA + row * PRSB + cb * 16), "l"(gb));
        }
        asm volatile("cp.async.commit_group;");
    };

    #pragma unroll
    for (int s = 0; s < 2; s++) load_stage(s, s);

    const uint32_t lrow = (lane & 15);
    const uint32_t lkb  = (lane >> 4) * 16;

    for (int i = 0; i < NK; i++) {
        asm volatile("cp.async.wait_group 1;");
        __syncthreads();
        int nxt = i + 2;
        if (nxt < NK) load_stage(nxt, nxt % 3);
        else          asm volatile("cp.async.commit_group;");

        const uint32_t sb = smem_base + (i % 3) * PSTAGE;
        const uint32_t abase = sb + (wm * 64) * PRSB;
        const uint32_t bbase = sb + PTILEA + (wn * 16) * PRSB;

        #pragma unroll
        for (int ks = 0; ks < 2; ks++) {
            uint32_t Af[4][4], Bf[4];
            #pragma unroll
            for (int mt = 0; mt < 4; mt++)
                LDSM_X4(Af[mt], abase + (mt * 16 + lrow) * PRSB + ks * 32 + lkb);
            LDSM_X4(Bf, bbase + lrow * PRSB + ks * 32 + lkb);

            #pragma unroll
            for (int mt = 0; mt < 4; mt++) {
                #pragma unroll
                for (int nt = 0; nt < 2; nt++) {
                    uint32_t b2[2] = { Bf[nt], Bf[nt + 2] };
                    MMA_F16(acc[mt][nt], Af[mt], b2);
                }
            }
        }
    }

    // transposed scatter: Wbig[n][colOff + k] = fp16(C[k][n])
    const int groupID = lane >> 2, tig = lane & 3;
    #pragma unroll
    for (int mt = 0; mt < 4; mt++) {
        #pragma unroll
        for (int nt = 0; nt < 2; nt++) {
            int r0 = m0 + wm * 64 + mt * 16 + groupID;
            int c0 = n0 + wn * 16 + nt * 8 + tig * 2;
            #pragma unroll
            for (int e = 0; e < 4; e++) {
                int r = r0 + (e >> 1) * 8;
                int c = c0 + (e & 1);
                Wbig[(size_t)c * Kb + colOff + r] = __float2half_rn(acc[mt][nt][e]);
            }
        }
    }
}

// ---------------- big GEMM: C[M,Nc] = A_fp16[M,K](lda) @ W_fp16[Nc,K]^T ----------------
// CTA 128x128, 8 warps (2M x 4N), warp 64x32, BK=32, 4-stage cp.async, 2 CTAs/SM.
#define BM 128
#define BN 128
#define RSB 80
#define TILE_B (BM * RSB)                        // 10240
#define STAGE  (2 * TILE_B)                      // 20480 (A | B)
#define GSM    (4 * STAGE)                       // 81920

template<bool HAS_BIAS, bool HAS_RES>
__global__ __launch_bounds__(256, 2)
void bgemm(const __half* __restrict__ A, int lda, const __half* __restrict__ Bw,
           int K, int Nc, float* __restrict__ Cf,
           const float* __restrict__ bias, const float* __restrict__ res)
{
    extern __shared__ __align__(128) char smem[];
    const int tid  = threadIdx.x;
    const int warp = tid >> 5, lane = tid & 31;
    const int wm = warp & 1, wn = warp >> 1;
    const int m0 = blockIdx.y * BM, n0 = blockIdx.x * BN;
    const uint32_t smem_base = cvta_smem(smem);

    const int NKP = K / 32;
    const size_t arow_bytes = (size_t)lda * 2;
    const size_t brow_bytes = (size_t)K * 2;
    const __half* Ab = A  + (size_t)m0 * lda;
    const __half* Bb = Bw + (size_t)n0 * K;

    float acc[4][4][4];
    #pragma unroll
    for (int i = 0; i < 4; i++)
        #pragma unroll
        for (int j = 0; j < 4; j++)
            #pragma unroll
            for (int e = 0; e < 4; e++) acc[i][j][e] = 0.f;

    auto load_stage = [&](int sk, int buf) {
        const uint32_t sb = smem_base + buf * STAGE;
        const size_t kb = (size_t)sk * 64;
        #pragma unroll
        for (int j = 0; j < 2; j++) {
            int chunk = tid + j * 256;
            int row = chunk >> 2, cb = chunk & 3;
            const char* ga = (const char*)Ab + (size_t)row * arow_bytes + kb + cb * 16;
            asm volatile("cp.async.cg.shared.global [%0], [%1], 16;"
                         :: "r"(sb + row * RSB + cb * 16), "l"(ga));
        }
        #pragma unroll
        for (int j = 0; j < 2; j++) {
            int chunk = tid + j * 256;
            int row = chunk >> 2, cb = chunk & 3;
            const char* gb = (const char*)Bb + (size_t)row * brow_bytes + kb + cb * 16;
            asm volatile("cp.async.cg.shared.global [%0], [%1], 16;"
                         :: "r"(sb + TILE_B + row * RSB + cb * 16), "l"(gb));
        }
        asm volatile("cp.async.commit_group;");
    };

    #pragma unroll
    for (int s = 0; s < 3; s++) load_stage(s, s);

    const uint32_t lrow = (lane & 15);
    const uint32_t lkb  = (lane >> 4) * 16;

    for (int i = 0; i < NKP; i++) {
        asm volatile("cp.async.wait_group 2;");
        __syncthreads();
        int nxt = i + 3;
        if (nxt < NKP) load_stage(nxt, nxt & 3);
        else           asm volatile("cp.async.commit_group;");

        const uint32_t sb = smem_base + (i & 3) * STAGE;
        const uint32_t abase = sb + (wm * 64) * RSB;
        const uint32_t bbase = sb + TILE_B + (wn * 32) * RSB;

        #pragma unroll
        for (int ks = 0; ks < 2; ks++) {
            uint32_t Af[4][4], Bf[2][4];
            #pragma unroll
            for (int mt = 0; mt < 4; mt++)
                LDSM_X4(Af[mt], abase + (mt * 16 + lrow) * RSB + ks * 32 + lkb);
            #pragma unroll
            for (int g = 0; g < 2; g++)
                LDSM_X4(Bf[g], bbase + (g * 16 + lrow) * RSB + ks * 32 + lkb);

            #pragma unroll
            for (int mt = 0; mt < 4; mt++)
                #pragma unroll
                for (int nt = 0; nt < 4; nt++) {
                    uint32_t b2[2] = { Bf[nt >> 1][nt & 1], Bf[nt >> 1][(nt & 1) + 2] };
                    MMA_F16(acc[mt][nt], Af[mt], b2);
                }
        }
    }
    __syncthreads();

    // ---- acc -> smem bounce -> fused coalesced epilogue ----
    float* stile = (float*)smem;               // [128][132]
    const int groupID = lane >> 2, tig = lane & 3;
    #pragma unroll
    for (int mt = 0; mt < 4; mt++) {
        int r0 = wm * 64 + mt * 16 + groupID;
        #pragma unroll
        for (int nt = 0; nt < 4; nt++) {
            int c = wn * 32 + nt * 8 + tig * 2;
            *(float2*)&stile[r0 * 132 + c]       = make_float2(acc[mt][nt][0], acc[mt][nt][1]);
            *(float2*)&stile[(r0 + 8) * 132 + c] = make_float2(acc[mt][nt][2], acc[mt][nt][3]);
        }
    }
    __syncthreads();

    float4 b4 = make_float4(0.f, 0.f, 0.f, 0.f);
    int col = n0 + lane * 4;
    if (HAS_BIAS) b4 = *(const float4*)(bias + col);

    #pragma unroll 4
    for (int rr = 0; rr < 16; rr++) {
        int r = warp * 16 + rr;
        int row = m0 + r;
        float4 v = *(float4*)&stile[r * 132 + lane * 4];
        if (HAS_BIAS) { v.x += b4.x; v.y += b4.y; v.z += b4.z; v.w += b4.w; }
        if (HAS_RES) {
            float4 r4 = *(const float4*)(res + (size_t)row * Nc + col);
            v.x += r4.x; v.y += r4.y; v.z += r4.z; v.w += r4.w;
        }
        *(float4*)(Cf + (size_t)row * Nc + col) = v;
    }
}

// ---------------- chunked scan (== FFT causal conv) ----------------
#define CHUNK 64
#define NCHUNK (SEQ_LEN / CHUNK)

__global__ __launch_bounds__(128) void scan1(const float* __restrict__ proj,
                                             const float* __restrict__ A_log,
                                             float* __restrict__ carry)
{
    int c = blockIdx.x, b = blockIdx.y, s = threadIdx.x;
    float lam = expf(-expf(A_log[s]));
    size_t row0 = (size_t)b * SEQ_LEN + c * CHUNK;
    float y = 0.f;
    #pragma unroll 8
    for (int t = 0; t < CHUNK; t++) {
        const float* p = proj + (row0 + t) * NPROJ;
        y = fmaf(lam, y, p[s] * p[128 + s]);
    }
    carry[(b * NCHUNK + c) * D_STATE + s] = y;
}

__global__ __launch_bounds__(128) void scan2(const float* __restrict__ A_log,
                                             float* __restrict__ carry)
{
    int b = blockIdx.x, s = threadIdx.x;
    float lam64 = expf(-expf(A_log[s]) * (float)CHUNK);
    float S = 0.f;
    for (int c = 0; c < NCHUNK; c++) {
        size_t i = (size_t)(b * NCHUNK + c) * D_STATE + s;
        float f = carry[i];
        carry[i] = S;
        S = fmaf(lam64, S, f);
    }
}

__global__ __launch_bounds__(128) void scan3(const float* __restrict__ proj,
                                             const float* __restrict__ A_log,
                                             const float* __restrict__ carry,
                                             __half* __restrict__ act)
{
    int c = blockIdx.x, b = blockIdx.y, s = threadIdx.x;
    float lam = expf(-expf(A_log[s]));
    float y = carry[(b * NCHUNK + c) * D_STATE + s];
    size_t row0 = (size_t)b * SEQ_LEN + c * CHUNK;
    #pragma unroll 4
    for (int t = 0; t < CHUNK; t++) {
        size_t row = row0 + t;
        const float* p = proj + row * NPROJ;
        y = fmaf(lam, y, p[s] * p[128 + s]);
        act[row * ACTW + D_MODEL + s] = __float2half_rn(y * p[256 + s]);
    }
}

// ---------------- launch ----------------
extern "C" void kernel_launch(void* const* d_in, const int* in_sizes, int n_in,
                              void* d_out, int out_size)
{
    const float* x        = (const float*)d_in[0];
    const float* ln_gamma = (const float*)d_in[1];
    const float* ln_beta  = (const float*)d_in[2];
    const float* W_in     = (const float*)d_in[3];
    const float* b_in     = (const float*)d_in[4];
    const float* W_xs     = (const float*)d_in[5];
    const float* W_B      = (const float*)d_in[6];
    const float* b_B      = (const float*)d_in[7];
    const float* W_C      = (const float*)d_in[8];
    const float* b_C      = (const float*)d_in[9];
    const float* A_log    = (const float*)d_in[10];
    const float* Dv       = (const float*)d_in[11];
    const float* W_so     = (const float*)d_in[12];
    const float* W_out    = (const float*)d_in[13];
    const float* b_out    = (const float*)d_in[14];
    float* out = (float*)d_out;

    __half *p_act, *p_WinA, *p_WcatA, *p_WpkB, *p_WoutB, *p_W4, *p_Wcat;
    float *p_proj, *p_b4, *p_b5, *p_carry;
    cudaGetSymbolAddress((void**)&p_act,   g_act);
    cudaGetSymbolAddress((void**)&p_proj,  g_proj);
    cudaGetSymbolAddress((void**)&p_WinA,  g_WinA);
    cudaGetSymbolAddress((void**)&p_WcatA, g_WcatA);
    cudaGetSymbolAddress((void**)&p_WpkB,  g_WpkB);
    cudaGetSymbolAddress((void**)&p_WoutB, g_WoutB);
    cudaGetSymbolAddress((void**)&p_W4,    g_W4);
    cudaGetSymbolAddress((void**)&p_Wcat,  g_Wcat);
    cudaGetSymbolAddress((void**)&p_b4,    g_b4);
    cudaGetSymbolAddress((void**)&p_b5,    g_b5);
    cudaGetSymbolAddress((void**)&p_carry, g_carry);

    cudaFuncSetAttribute(pgemm, cudaFuncAttributeMaxDynamicSharedMemorySize, PGSM);
    cudaFuncSetAttribute(bgemm<true, false>, cudaFuncAttributeMaxDynamicSharedMemorySize, GSM);
    cudaFuncSetAttribute(bgemm<true, true >, cudaFuncAttributeMaxDynamicSharedMemorySize, GSM);

    // ---- stream fork: precompute off the critical path ----
    cudaStream_t s2, s3;
    cudaStreamCreate(&s2);
    cudaStreamCreate(&s3);
    cudaEvent_t ev0, ev2, ev3;
    cudaEventCreateWithFlags(&ev0, cudaEventDisableTiming);
    cudaEventCreateWithFlags(&ev2, cudaEventDisableTiming);
    cudaEventCreateWithFlags(&ev3, cudaEventDisableTiming);

    cudaEventRecord(ev0, 0);
    cudaStreamWaitEvent(s2, ev0, 0);
    cudaStreamWaitEvent(s3, ev0, 0);

    // s2: W4 chain (needed before proj GEMM)
    prep_w4_side<<<(N_W4PREP + 255) / 256, 256, 0, s2>>>(W_in, W_xs, W_B, W_C, p_WinA, p_WpkB);
    pgemm<<<dim3(NPROJ / PBN, D_MODEL / PBM), 256, PGSM, s2>>>(p_WinA, p_WpkB, D_MODEL, p_W4, D_MODEL, 0);
    bias4_k<<<NPROJ, 128, 0, s2>>>(b_in, W_xs, W_B, b_B, W_C, b_C, p_b4);
    cudaEventRecord(ev2, s2);

    // s3: Wcat chain (needed before out GEMM)
    prep_wcat_side<<<(N_WCATPREP + 255) / 256, 256, 0, s3>>>(W_in, Dv, W_so, W_out, p_WcatA, p_WoutB);
    pgemm<<<dim3(D_MODEL / PBN, KCAT / PBM), 256, PGSM, s3>>>(p_WcatA, p_WoutB, D_MODEL, p_Wcat, KCAT, 0);
    bias5_k<<<D_MODEL, 128, 0, s3>>>(b_in, Dv, W_out, b_out, p_b5);
    cudaEventRecord(ev3, s3);

    // main: LayerNorm -> act[:, 0:1024]
    ln_h_kernel<<<ROWS, 256>>>(x, ln_gamma, ln_beta, p_act);

    // join W4 chain, then proj = xn @ W4 + b4
    cudaStreamWaitEvent(0, ev2, 0);
    bgemm<true, false><<<dim3(NPROJ / BN, ROWS / BM), 256, GSM>>>(
        p_act, ACTW, p_W4, D_MODEL, NPROJ, p_proj, p_b4, nullptr);

    // chunked linear recurrence (== FFT causal conv) -> act[:, 1024:1152]
    scan1<<<dim3(NCHUNK, BATCH), 128>>>(p_proj, A_log, p_carry);
    scan2<<<BATCH, 128>>>(A_log, p_carry);
    scan3<<<dim3(NCHUNK, BATCH), 128>>>(p_proj, A_log, p_carry, p_act);

    // join Wcat chain, then out = [xn | ysc] @ Wcat + b5 + x
    cudaStreamWaitEvent(0, ev3, 0);
    bgemm<true, true><<<dim3(D_MODEL / BN, ROWS / BM), 256, GSM>>>(
        p_act, ACTW, p_Wcat, KOUT, D_MODEL, out, p_b5, x);

    cudaEventDestroy(ev0);
    cudaEventDestroy(ev2);
    cudaEventDestroy(ev3);
    cudaStreamDestroy(s2);
    cudaStreamDestroy(s3);
}

// round 14
// speedup vs baseline: 4.7654x; 1.1265x over previous
#include <cuda_runtime.h>
#include <cuda_fp16.h>
#include <math.h>
#include <stdint.h>

#define D_MODEL 1024
#define D_STATE 128
#define SEQ_LEN 4096
#define BATCH   4
#define ROWS    (BATCH * SEQ_LEN)        // 16384
#define LN_EPS  1e-3f
#define NPROJ   384
#define ACTW    1152                     // [xn(1024) | ysc(128)]
#define KOUT    1152
#define KCAT    1152
#define SK_W4   6
#define SK_WC   2

// ---------------- scratch (allocation-free: __device__ globals) ----------------
__device__ __half g_act [(size_t)ROWS * ACTW];
__device__ float  g_proj[(size_t)ROWS * NPROJ];
__device__ __half g_WinA [(size_t)D_MODEL * 2 * D_MODEL];
__device__ __half g_WcatA[(size_t)KCAT    * 2 * D_MODEL];
__device__ __half g_WpkB [(size_t)NPROJ   * 2 * D_MODEL];
__device__ __half g_WoutB[(size_t)D_MODEL * 2 * D_MODEL];
__device__ float  g_W4part [(size_t)SK_W4 * NPROJ   * D_MODEL];   // 9.4 MB
__device__ float  g_WcatPart[(size_t)SK_WC * D_MODEL * KCAT];     // 9.4 MB
__device__ __half g_W4  [(size_t)NPROJ   * D_MODEL];
__device__ __half g_Wcat[(size_t)D_MODEL * KCAT];
__device__ float g_b4[NPROJ];
__device__ float g_b5[D_MODEL];
__device__ float g_carry[BATCH * 64 * D_STATE];

// ---------------- helpers ----------------
__device__ __forceinline__ uint32_t cvta_smem(const void* p) {
    uint32_t a;
    asm("{ .reg .u64 t; cvta.to.shared.u64 t, %1; cvt.u32.u64 %0, t; }" : "=r"(a) : "l"(p));
    return a;
}
__device__ __forceinline__ uint32_t pack_h2(__half a, __half b) {
    __half2 t; t.x = a; t.y = b;
    return *reinterpret_cast<uint32_t*>(&t);
}
__device__ __forceinline__ void split_store(__half* dst, size_t base, int K, int k, float w) {
    __half hi = __float2half_rn(w);
    __half lo = __float2half_rn(w - __half2float(hi));
    dst[base + k]     = hi;
    dst[base + K + k] = lo;
}

#define MMA_F16(d, a, b) \
    asm volatile( \
        "mma.sync.aligned.m16n8k16.row.col.f32.f16.f16.f32 " \
        "{%0,%1,%2,%3}, {%4,%5,%6,%7}, {%8,%9}, {%0,%1,%2,%3};" \
        : "+f"((d)[0]), "+f"((d)[1]), "+f"((d)[2]), "+f"((d)[3]) \
        : "r"((a)[0]), "r"((a)[1]), "r"((a)[2]), "r"((a)[3]), \
          "r"((b)[0]), "r"((b)[1]))

#define LDSM_X4(r, addr) \
    asm volatile("ldmatrix.sync.aligned.m8n8.x4.shared.b16 {%0,%1,%2,%3}, [%4];" \
        : "=r"((r)[0]), "=r"((r)[1]), "=r"((r)[2]), "=r"((r)[3]) : "r"(addr))

// ---------------- LayerNorm -> fp16 into g_act (stride ACTW) ----------------
__global__ __launch_bounds__(256) void ln_h_kernel(
    const float* __restrict__ x, const float* __restrict__ gamma,
    const float* __restrict__ beta, __half* __restrict__ act)
{
    int row = blockIdx.x;
    int tid = threadIdx.x;
    const float4* xr = (const float4*)(x + (size_t)row * D_MODEL);
    float4 v = xr[tid];

    float s  = v.x + v.y + v.z + v.w;
    float sq = v.x*v.x + v.y*v.y + v.z*v.z + v.w*v.w;
    #pragma unroll
    for (int o = 16; o > 0; o >>= 1) {
        s  += __shfl_xor_sync(0xffffffffu, s,  o);
        sq += __shfl_xor_sync(0xffffffffu, sq, o);
    }
    __shared__ float sh_s[8], sh_q[8];
    int wid = tid >> 5, lid = tid & 31;
    if (lid == 0) { sh_s[wid] = s; sh_q[wid] = sq; }
    __syncthreads();
    if (wid == 0) {
        float a = (lid < 8) ? sh_s[lid] : 0.f;
        float b = (lid < 8) ? sh_q[lid] : 0.f;
        #pragma unroll
        for (int o = 4; o > 0; o >>= 1) {
            a += __shfl_xor_sync(0xffffffffu, a, o);
            b += __shfl_xor_sync(0xffffffffu, b, o);
        }
        if (lid == 0) { sh_s[0] = a; sh_q[0] = b; }
    }
    __syncthreads();
    float mu   = sh_s[0] * (1.0f / D_MODEL);
    float var  = sh_q[0] * (1.0f / D_MODEL) - mu * mu;
    float rstd = rsqrtf(var + LN_EPS);

    float4 gv = ((const float4*)gamma)[tid];
    float4 bv = ((const float4*)beta)[tid];
    float o0 = (v.x - mu) * rstd * gv.x + bv.x;
    float o1 = (v.y - mu) * rstd * gv.y + bv.y;
    float o2 = (v.z - mu) * rstd * gv.z + bv.z;
    float o3 = (v.w - mu) * rstd * gv.w + bv.w;

    uint2 hv = make_uint2(pack_h2(__float2half_rn(o0), __float2half_rn(o1)),
                          pack_h2(__float2half_rn(o2), __float2half_rn(o3)));
    *(uint2*)(act + (size_t)row * ACTW + tid * 4) = hv;
}

// ---------------- A-side preps (coalesced, elementwise) ----------------
__global__ void prepA_win(const float* __restrict__ W_in, __half* __restrict__ WinA)
{
    int idx = blockIdx.x * blockDim.x + threadIdx.x;
    if (idx >= D_MODEL * D_MODEL) return;
    int m = idx >> 10, k = idx & 1023;
    split_store(WinA, (size_t)m * 2 * D_MODEL, D_MODEL, k, W_in[idx]);
}

__global__ void prepA_cat(const float* __restrict__ W_in, const float* __restrict__ D,
                          const float* __restrict__ W_so, __half* __restrict__ WcatA)
{
    int idx = blockIdx.x * blockDim.x + threadIdx.x;
    if (idx >= KCAT * D_MODEL) return;
    int m = idx >> 10, j = idx & 1023;
    float w = (m < D_MODEL) ? (W_in[(size_t)m * D_MODEL + j] * D[j])
                            : W_so[(size_t)(m - D_MODEL) * D_MODEL + j];
    split_store(WcatA, (size_t)m * 2 * D_MODEL, D_MODEL, j, w);
}

// ---------------- B-side preps: tiled transpose + split (coalesced both sides) ----------------
// dst[n][2K] hi/lo from src[k][n]-style layouts.
__global__ __launch_bounds__(256) void tsplit_pk(
    const float* __restrict__ Wxs, const float* __restrict__ WB,
    const float* __restrict__ WC, __half* __restrict__ dst)
{
    __shared__ float t[32][33];
    int tx = threadIdx.x, ty = threadIdx.y;      // (32, 8)
    int n0 = blockIdx.x * 32, k0 = blockIdx.y * 32;
    #pragma unroll
    for (int i = 0; i < 4; i++) {
        int n = n0 + tx;
        int c = n & 127;
        const float* src = (n < 128) ? Wxs : ((n < 256) ? WB : WC);
        t[ty + 8 * i][tx] = src[(size_t)(k0 + ty + 8 * i) * 128 + c];
    }
    __syncthreads();
    #pragma unroll
    for (int i = 0; i < 4; i++) {
        int n = n0 + ty + 8 * i, k = k0 + tx;
        split_store(dst, (size_t)n * 2 * D_MODEL, D_MODEL, k, t[tx][ty + 8 * i]);
    }
}

__global__ __launch_bounds__(256) void tsplit_out(
    const float* __restrict__ W, __half* __restrict__ dst)
{
    __shared__ float t[32][33];
    int tx = threadIdx.x, ty = threadIdx.y;
    int n0 = blockIdx.x * 32, k0 = blockIdx.y * 32;
    #pragma unroll
    for (int i = 0; i < 4; i++)
        t[ty + 8 * i][tx] = W[(size_t)(k0 + ty + 8 * i) * D_MODEL + n0 + tx];
    __syncthreads();
    #pragma unroll
    for (int i = 0; i < 4; i++) {
        int n = n0 + ty + 8 * i, k = k0 + tx;
        split_store(dst, (size_t)n * 2 * D_MODEL, D_MODEL, k, t[tx][ty + 8 * i]);
    }
}

// ---------------- bias reductions (block per output) ----------------
__global__ __launch_bounds__(128) void bias4_k(const float* __restrict__ b_in,
                        const float* __restrict__ W_xs, const float* __restrict__ W_B,
                        const float* __restrict__ bB,  const float* __restrict__ W_C,
                        const float* __restrict__ bC,  float* __restrict__ b4)
{
    __shared__ float sh[4];
    int n = blockIdx.x, tid = threadIdx.x;
    const float* W; const float* badd = nullptr; int c = n;
    if (n < 128)      { W = W_xs; }
    else if (n < 256) { W = W_B; c = n - 128; badd = bB; }
    else              { W = W_C; c = n - 256; badd = bC; }
    float acc = 0.f;
    for (int j = tid; j < D_MODEL; j += 128) acc += b_in[j] * W[(size_t)j * 128 + c];
    #pragma unroll
    for (int o = 16; o > 0; o >>= 1) acc += __shfl_xor_sync(0xffffffffu, acc, o);
    if ((tid & 31) == 0) sh[tid >> 5] = acc;
    __syncthreads();
    if (tid == 0) {
        float t = sh[0] + sh[1] + sh[2] + sh[3];
        b4[n] = t + (badd ? badd[c] : 0.f);
    }
}

__global__ __launch_bounds__(128) void bias5_k(const float* __restrict__ b_in,
                        const float* __restrict__ D, const float* __restrict__ W_out,
                        const float* __restrict__ b_out, float* __restrict__ b5)
{
    __shared__ float sh[4];
    int n = blockIdx.x, tid = threadIdx.x;
    float acc = 0.f;
    for (int j = tid; j < D_MODEL; j += 128)
        acc += b_in[j] * D[j] * W_out[(size_t)j * D_MODEL + n];
    #pragma unroll
    for (int o = 16; o > 0; o >>= 1) acc += __shfl_xor_sync(0xffffffffu, acc, o);
    if ((tid & 31) == 0) sh[tid >> 5] = acc;
    __syncthreads();
    if (tid == 0) b5[n] = sh[0] + sh[1] + sh[2] + sh[3] + b_out[n];
}

// ---------------- precompute GEMM (3-term fp16 dual split, split-K -> fp32 partials) ----------------
#define PBM 128
#define PBN 64
#define PRSB 80
#define PTILEA (PBM * PRSB)
#define PSTAGE ((PBM + PBN) * PRSB)
#define PGSM (3 * PSTAGE)

__global__ __launch_bounds__(256, 2)
void pgemm(const __half* __restrict__ A, const __half* __restrict__ B, int K,
           float* __restrict__ Wpart, int Nc, int ldw, int chunks_per)
{
    extern __shared__ __align__(128) char smem[];
    const int tid  = threadIdx.x;
    const int warp = tid >> 5, lane = tid & 31;
    const int wm = warp & 1, wn = warp >> 1;
    const int m0 = blockIdx.y * PBM, n0 = blockIdx.x * PBN;
    const int z  = blockIdx.z;
    const int c0 = z * chunks_per;
    const uint32_t smem_base = cvta_smem(smem);

    const int KB = K / 32;
    const size_t row_bytes = (size_t)K * 4;
    const __half* Ab = A + (size_t)m0 * 2 * K;
    const __half* Bb = B + (size_t)n0 * 2 * K;

    float acc[4][2][4];
    #pragma unroll
    for (int i = 0; i < 4; i++)
        #pragma unroll
        for (int j = 0; j < 2; j++)
            #pragma unroll
            for (int e = 0; e < 4; e++) acc[i][j][e] = 0.f;

    auto load_stage = [&](int sk, int buf) {
        const uint32_t sb = smem_base + buf * PSTAGE;
        int lkA = (sk < 2 * KB) ? sk : sk - 2 * KB;   // A: [hi|lo|hi]
        int lkB = (sk < KB)     ? sk : sk - KB;       // B: [hi|hi|lo]
        const size_t kbA = (size_t)lkA * 64;
        const size_t kbB = (size_t)lkB * 64;
        #pragma unroll
        for (int j = 0; j < 2; j++) {
            int chunk = tid + j * 256;
            int row = chunk >> 2, cb = chunk & 3;
            const char* ga = (const char*)Ab + (size_t)row * row_bytes + kbA + cb * 16;
            asm volatile("cp.async.cg.shared.global [%0], [%1], 16;"
                         :: "r"(sb + row * PRSB + cb * 16), "l"(ga));
        }
        {
            int row = tid >> 2, cb = tid & 3;
            const char* gb = (const char*)Bb + (size_t)row * row_bytes + kbB + cb * 16;
            asm volatile("cp.async.cg.shared.global [%0], [%1], 16;"
                         :: "r"(sb + PTILEA + row * PRSB + cb * 16), "l"(gb));
        }
        asm volatile("cp.async.commit_group;");
    };

    #pragma unroll
    for (int s = 0; s < 2; s++) load_stage(c0 + s, s);

    const uint32_t lrow = (lane & 15);
    const uint32_t lkb  = (lane >> 4) * 16;

    for (int i = 0; i < chunks_per; i++) {
        asm volatile("cp.async.wait_group 1;");
        __syncthreads();
        int nxt = i + 2;
        if (nxt < chunks_per) load_stage(c0 + nxt, nxt % 3);
        else                  asm volatile("cp.async.commit_group;");

        const uint32_t sb = smem_base + (i % 3) * PSTAGE;
        const uint32_t abase = sb + (wm * 64) * PRSB;
        const uint32_t bbase = sb + PTILEA + (wn * 16) * PRSB;

        #pragma unroll
        for (int ks = 0; ks < 2; ks++) {
            uint32_t Af[4][4], Bf[4];
            #pragma unroll
            for (int mt = 0; mt < 4; mt++)
                LDSM_X4(Af[mt], abase + (mt * 16 + lrow) * PRSB + ks * 32 + lkb);
            LDSM_X4(Bf, bbase + lrow * PRSB + ks * 32 + lkb);

            #pragma unroll
            for (int mt = 0; mt < 4; mt++) {
                #pragma unroll
                for (int nt = 0; nt < 2; nt++) {
                    uint32_t b2[2] = { Bf[nt], Bf[nt + 2] };
                    MMA_F16(acc[mt][nt], Af[mt], b2);
                }
            }
        }
    }

    // scatter fp32 partial: Wpart[z][n][k]   (n = C col, k = C row)
    float* Wp = Wpart + (size_t)z * Nc * ldw;
    const int groupID = lane >> 2, tig = lane & 3;
    #pragma unroll
    for (int mt = 0; mt < 4; mt++) {
        #pragma unroll
        for (int nt = 0; nt < 2; nt++) {
            int r0 = m0 + wm * 64 + mt * 16 + groupID;
            int c0c = n0 + wn * 16 + nt * 8 + tig * 2;
            #pragma unroll
            for (int e = 0; e < 4; e++) {
                int r = r0 + (e >> 1) * 8;
                int c = c0c + (e & 1);
                Wp[(size_t)c * ldw + r] = acc[mt][nt][e];
            }
        }
    }
}

// ---------------- reduce partials -> fp16 weight ----------------
__global__ void reduce_quant(const float* __restrict__ part, int S, size_t plane,
                             __half* __restrict__ dst, int n)
{
    int idx = blockIdx.x * blockDim.x + threadIdx.x;
    if (idx >= n) return;
    float s = 0.f;
    for (int z = 0; z < S; z++) s += part[(size_t)z * plane + idx];
    dst[idx] = __float2half_rn(s);
}

// ---------------- big GEMM: C[M,Nc] = A_fp16[M,K](lda) @ W_fp16[Nc,K]^T ----------------
#define BM 128
#define BN 128
#define RSB 80
#define TILE_B (BM * RSB)
#define STAGE  (2 * TILE_B)
#define GSM    (4 * STAGE)                       // 81920

template<bool HAS_BIAS, bool HAS_RES>
__global__ __launch_bounds__(256, 2)
void bgemm(const __half* __restrict__ A, int lda, const __half* __restrict__ Bw,
           int K, int Nc, float* __restrict__ Cf,
           const float* __restrict__ bias, const float* __restrict__ res)
{
    extern __shared__ __align__(128) char smem[];
    const int tid  = threadIdx.x;
    const int warp = tid >> 5, lane = tid & 31;
    const int wm = warp & 1, wn = warp >> 1;
    const int m0 = blockIdx.y * BM, n0 = blockIdx.x * BN;
    const uint32_t smem_base = cvta_smem(smem);

    const int NKP = K / 32;
    const size_t arow_bytes = (size_t)lda * 2;
    const size_t brow_bytes = (size_t)K * 2;
    const __half* Ab = A  + (size_t)m0 * lda;
    const __half* Bb = Bw + (size_t)n0 * K;

    float acc[4][4][4];
    #pragma unroll
    for (int i = 0; i < 4; i++)
        #pragma unroll
        for (int j = 0; j < 4; j++)
            #pragma unroll
            for (int e = 0; e < 4; e++) acc[i][j][e] = 0.f;

    auto load_stage = [&](int sk, int buf) {
        const uint32_t sb = smem_base + buf * STAGE;
        const size_t kb = (size_t)sk * 64;
        #pragma unroll
        for (int j = 0; j < 2; j++) {
            int chunk = tid + j * 256;
            int row = chunk >> 2, cb = chunk & 3;
            const char* ga = (const char*)Ab + (size_t)row * arow_bytes + kb + cb * 16;
            asm volatile("cp.async.cg.shared.global [%0], [%1], 16;"
                         :: "r"(sb + row * RSB + cb * 16), "l"(ga));
        }
        #pragma unroll
        for (int j = 0; j < 2; j++) {
            int chunk = tid + j * 256;
            int row = chunk >> 2, cb = chunk & 3;
            const char* gb = (const char*)Bb + (size_t)row * brow_bytes + kb + cb * 16;
            asm volatile("cp.async.cg.shared.global [%0], [%1], 16;"
                         :: "r"(sb + TILE_B + row * RSB + cb * 16), "l"(gb));
        }
        asm volatile("cp.async.commit_group;");
    };

    #pragma unroll
    for (int s = 0; s < 3; s++) load_stage(s, s);

    const uint32_t lrow = (lane & 15);
    const uint32_t lkb  = (lane >> 4) * 16;

    for (int i = 0; i < NKP; i++) {
        asm volatile("cp.async.wait_group 2;");
        __syncthreads();
        int nxt = i + 3;
        if (nxt < NKP) load_stage(nxt, nxt & 3);
        else           asm volatile("cp.async.commit_group;");

        const uint32_t sb = smem_base + (i & 3) * STAGE;
        const uint32_t abase = sb + (wm * 64) * RSB;
        const uint32_t bbase = sb + TILE_B + (wn * 32) * RSB;

        #pragma unroll
        for (int ks = 0; ks < 2; ks++) {
            uint32_t Af[4][4], Bf[2][4];
            #pragma unroll
            for (int mt = 0; mt < 4; mt++)
                LDSM_X4(Af[mt], abase + (mt * 16 + lrow) * RSB + ks * 32 + lkb);
            #pragma unroll
            for (int g = 0; g < 2; g++)
                LDSM_X4(Bf[g], bbase + (g * 16 + lrow) * RSB + ks * 32 + lkb);

            #pragma unroll
            for (int mt = 0; mt < 4; mt++)
                #pragma unroll
                for (int nt = 0; nt < 4; nt++) {
                    uint32_t b2[2] = { Bf[nt >> 1][nt & 1], Bf[nt >> 1][(nt & 1) + 2] };
                    MMA_F16(acc[mt][nt], Af[mt], b2);
                }
        }
    }
    __syncthreads();

    // ---- acc -> smem bounce -> fused coalesced epilogue ----
    float* stile = (float*)smem;               // [128][132]
    const int groupID = lane >> 2, tig = lane & 3;
    #pragma unroll
    for (int mt = 0; mt < 4; mt++) {
        int r0 = wm * 64 + mt * 16 + groupID;
        #pragma unroll
        for (int nt = 0; nt < 4; nt++) {
            int c = wn * 32 + nt * 8 + tig * 2;
            *(float2*)&stile[r0 * 132 + c]       = make_float2(acc[mt][nt][0], acc[mt][nt][1]);
            *(float2*)&stile[(r0 + 8) * 132 + c] = make_float2(acc[mt][nt][2], acc[mt][nt][3]);
        }
    }
    __syncthreads();

    float4 b4 = make_float4(0.f, 0.f, 0.f, 0.f);
    int col = n0 + lane * 4;
    if (HAS_BIAS) b4 = *(const float4*)(bias + col);

    #pragma unroll 4
    for (int rr = 0; rr < 16; rr++) {
        int r = warp * 16 + rr;
        int row = m0 + r;
        float4 v = *(float4*)&stile[r * 132 + lane * 4];
        if (HAS_BIAS) { v.x += b4.x; v.y += b4.y; v.z += b4.z; v.w += b4.w; }
        if (HAS_RES) {
            float4 r4 = *(const float4*)(res + (size_t)row * Nc + col);
            v.x += r4.x; v.y += r4.y; v.z += r4.z; v.w += r4.w;
        }
        *(float4*)(Cf + (size_t)row * Nc + col) = v;
    }
}

// ---------------- chunked scan (== FFT causal conv) ----------------
#define CHUNK 64
#define NCHUNK (SEQ_LEN / CHUNK)

__global__ __launch_bounds__(128) void scan1(const float* __restrict__ proj,
                                             const float* __restrict__ A_log,
                                             float* __restrict__ carry)
{
    int c = blockIdx.x, b = blockIdx.y, s = threadIdx.x;
    float lam = expf(-expf(A_log[s]));
    size_t row0 = (size_t)b * SEQ_LEN + c * CHUNK;
    float y = 0.f;
    #pragma unroll 8
    for (int t = 0; t < CHUNK; t++) {
        const float* p = proj + (row0 + t) * NPROJ;
        y = fmaf(lam, y, p[s] * p[128 + s]);
    }
    carry[(b * NCHUNK + c) * D_STATE + s] = y;
}

__global__ __launch_bounds__(128) void scan2(const float* __restrict__ A_log,
                                             float* __restrict__ carry)
{
    int b = blockIdx.x, s = threadIdx.x;
    float lam64 = expf(-expf(A_log[s]) * (float)CHUNK);
    float S = 0.f;
    for (int c = 0; c < NCHUNK; c++) {
        size_t i = (size_t)(b * NCHUNK + c) * D_STATE + s;
        float f = carry[i];
        carry[i] = S;
        S = fmaf(lam64, S, f);
    }
}

__global__ __launch_bounds__(128) void scan3(const float* __restrict__ proj,
                                             const float* __restrict__ A_log,
                                             const float* __restrict__ carry,
                                             __half* __restrict__ act)
{
    int c = blockIdx.x, b = blockIdx.y, s = threadIdx.x;
    float lam = expf(-expf(A_log[s]));
    float y = carry[(b * NCHUNK + c) * D_STATE + s];
    size_t row0 = (size_t)b * SEQ_LEN + c * CHUNK;
    #pragma unroll 4
    for (int t = 0; t < CHUNK; t++) {
        size_t row = row0 + t;
        const float* p = proj + row * NPROJ;
        y = fmaf(lam, y, p[s] * p[128 + s]);
        act[row * ACTW + D_MODEL + s] = __float2half_rn(y * p[256 + s]);
    }
}

// ---------------- launch ----------------
extern "C" void kernel_launch(void* const* d_in, const int* in_sizes, int n_in,
                              void* d_out, int out_size)
{
    const float* x        = (const float*)d_in[0];
    const float* ln_gamma = (const float*)d_in[1];
    const float* ln_beta  = (const float*)d_in[2];
    const float* W_in     = (const float*)d_in[3];
    const float* b_in     = (const float*)d_in[4];
    const float* W_xs     = (const float*)d_in[5];
    const float* W_B      = (const float*)d_in[6];
    const float* b_B      = (const float*)d_in[7];
    const float* W_C      = (const float*)d_in[8];
    const float* b_C      = (const float*)d_in[9];
    const float* A_log    = (const float*)d_in[10];
    const float* Dv       = (const float*)d_in[11];
    const float* W_so     = (const float*)d_in[12];
    const float* W_out    = (const float*)d_in[13];
    const float* b_out    = (const float*)d_in[14];
    float* out = (float*)d_out;

    __half *p_act, *p_WinA, *p_WcatA, *p_WpkB, *p_WoutB, *p_W4, *p_Wcat;
    float *p_proj, *p_W4part, *p_WcatPart, *p_b4, *p_b5, *p_carry;
    cudaGetSymbolAddress((void**)&p_act,      g_act);
    cudaGetSymbolAddress((void**)&p_proj,     g_proj);
    cudaGetSymbolAddress((void**)&p_WinA,     g_WinA);
    cudaGetSymbolAddress((void**)&p_WcatA,    g_WcatA);
    cudaGetSymbolAddress((void**)&p_WpkB,     g_WpkB);
    cudaGetSymbolAddress((void**)&p_WoutB,    g_WoutB);
    cudaGetSymbolAddress((void**)&p_W4part,   g_W4part);
    cudaGetSymbolAddress((void**)&p_WcatPart, g_WcatPart);
    cudaGetSymbolAddress((void**)&p_W4,       g_W4);
    cudaGetSymbolAddress((void**)&p_Wcat,     g_Wcat);
    cudaGetSymbolAddress((void**)&p_b4,       g_b4);
    cudaGetSymbolAddress((void**)&p_b5,       g_b5);
    cudaGetSymbolAddress((void**)&p_carry,    g_carry);

    cudaFuncSetAttribute(pgemm, cudaFuncAttributeMaxDynamicSharedMemorySize, PGSM);
    cudaFuncSetAttribute(bgemm<true, false>, cudaFuncAttributeMaxDynamicSharedMemorySize, GSM);
    cudaFuncSetAttribute(bgemm<true, true >, cudaFuncAttributeMaxDynamicSharedMemorySize, GSM);

    // ---- stream fork: precompute off the critical path ----
    cudaStream_t s2, s3;
    cudaStreamCreate(&s2);
    cudaStreamCreate(&s3);
    cudaEvent_t ev0, ev2, ev3;
    cudaEventCreateWithFlags(&ev0, cudaEventDisableTiming);
    cudaEventCreateWithFlags(&ev2, cudaEventDisableTiming);
    cudaEventCreateWithFlags(&ev3, cudaEventDisableTiming);

    cudaEventRecord(ev0, 0);
    cudaStreamWaitEvent(s2, ev0, 0);
    cudaStreamWaitEvent(s3, ev0, 0);

    // s2: W4 chain (needed before proj GEMM)
    prepA_win<<<(D_MODEL * D_MODEL + 255) / 256, 256, 0, s2>>>(W_in, p_WinA);
    tsplit_pk<<<dim3(NPROJ / 32, D_MODEL / 32), dim3(32, 8), 0, s2>>>(W_xs, W_B, W_C, p_WpkB);
    bias4_k<<<NPROJ, 128, 0, s2>>>(b_in, W_xs, W_B, b_B, W_C, b_C, p_b4);
    pgemm<<<dim3(NPROJ / PBN, D_MODEL / PBM, SK_W4), 256, PGSM, s2>>>(
        p_WinA, p_WpkB, D_MODEL, p_W4part, NPROJ, D_MODEL, (3 * D_MODEL / 32) / SK_W4);
    reduce_quant<<<(NPROJ * D_MODEL + 255) / 256, 256, 0, s2>>>(
        p_W4part, SK_W4, (size_t)NPROJ * D_MODEL, p_W4, NPROJ * D_MODEL);
    cudaEventRecord(ev2, s2);

    // s3: Wcat chain (needed before out GEMM)
    prepA_cat<<<(KCAT * D_MODEL + 255) / 256, 256, 0, s3>>>(W_in, Dv, W_so, p_WcatA);
    tsplit_out<<<dim3(D_MODEL / 32, D_MODEL / 32), dim3(32, 8), 0, s3>>>(W_out, p_WoutB);
    bias5_k<<<D_MODEL, 128, 0, s3>>>(b_in, Dv, W_out, b_out, p_b5);
    pgemm<<<dim3(D_MODEL / PBN, KCAT / PBM, SK_WC), 256, PGSM, s3>>>(
        p_WcatA, p_WoutB, D_MODEL, p_WcatPart, D_MODEL, KCAT, (3 * D_MODEL / 32) / SK_WC);
    reduce_quant<<<(D_MODEL * KCAT + 255) / 256, 256, 0, s3>>>(
        p_WcatPart, SK_WC, (size_t)D_MODEL * KCAT, p_Wcat, D_MODEL * KCAT);
    cudaEventRecord(ev3, s3);

    // main: LayerNorm -> act[:, 0:1024]
    ln_h_kernel<<<ROWS, 256>>>(x, ln_gamma, ln_beta, p_act);

    // join W4 chain, then proj = xn @ W4 + b4
    cudaStreamWaitEvent(0, ev2, 0);
    bgemm<true, false><<<dim3(NPROJ / BN, ROWS / BM), 256, GSM>>>(
        p_act, ACTW, p_W4, D_MODEL, NPROJ, p_proj, p_b4, nullptr);

    // chunked linear recurrence (== FFT causal conv) -> act[:, 1024:1152]
    scan1<<<dim3(NCHUNK, BATCH), 128>>>(p_proj, A_log, p_carry);
    scan2<<<BATCH, 128>>>(A_log, p_carry);
    scan3<<<dim3(NCHUNK, BATCH), 128>>>(p_proj, A_log, p_carry, p_act);

    // join Wcat chain, then out = [xn | ysc] @ Wcat + b5 + x
    cudaStreamWaitEvent(0, ev3, 0);
    bgemm<true, true><<<dim3(D_MODEL / BN, ROWS / BM), 256, GSM>>>(
        p_act, ACTW, p_Wcat, KOUT, D_MODEL, out, p_b5, x);

    cudaEventDestroy(ev0);
    cudaEventDestroy(ev2);
    cudaEventDestroy(ev3);
    cudaStreamDestroy(s2);
    cudaStreamDestroy(s3);
}